// round 2
// baseline (speedup 1.0000x reference)
#include <cuda_runtime.h>
#include <math.h>

// Problem constants (shape-fixed per registry; derived dynamically in launch too)
#define MAXN 65536
#define MAXM 2048
#define MAXK 512

// Static scratch (allocation-free rule: __device__ globals)
__device__ float g_A [(size_t)MAXN * MAXK];   // 128 MB : LN'd RNA projection
__device__ float g_S [(size_t)MAXN * MAXM];   // 512 MB : scores / probs
__device__ float g_Dp[(size_t)MAXK * MAXM];   //   4 MB : LN'd drug projection

#define LN_EPS 1e-5f

// ---------------- block reduce helpers ----------------
__device__ __forceinline__ float blockReduceSum(float v, volatile float* sm) {
    int lane = threadIdx.x & 31, w = threadIdx.x >> 5;
    #pragma unroll
    for (int o = 16; o; o >>= 1) v += __shfl_xor_sync(0xffffffffu, v, o);
    __syncthreads();
    if (lane == 0) sm[w] = v;
    __syncthreads();
    if (w == 0) {
        float x = (lane < (int)(blockDim.x >> 5)) ? sm[lane] : 0.f;
        #pragma unroll
        for (int o = 16; o; o >>= 1) x += __shfl_xor_sync(0xffffffffu, x, o);
        if (lane == 0) sm[0] = x;
    }
    __syncthreads();
    float r = sm[0];
    __syncthreads();
    return r;
}

__device__ __forceinline__ float blockReduceMax(float v, volatile float* sm) {
    int lane = threadIdx.x & 31, w = threadIdx.x >> 5;
    #pragma unroll
    for (int o = 16; o; o >>= 1) v = fmaxf(v, __shfl_xor_sync(0xffffffffu, v, o));
    __syncthreads();
    if (lane == 0) sm[w] = v;
    __syncthreads();
    if (w == 0) {
        float x = (lane < (int)(blockDim.x >> 5)) ? sm[lane] : -INFINITY;
        #pragma unroll
        for (int o = 16; o; o >>= 1) x = fmaxf(x, __shfl_xor_sync(0xffffffffu, x, o));
        if (lane == 0) sm[0] = x;
    }
    __syncthreads();
    float r = sm[0];
    __syncthreads();
    return r;
}

// ---------------- generic 128x128x8 SGEMM, 8x8 microtile ----------------
// C[M,N] = A[M,K] @ B[K,N], all row-major. Requires M%128==0, N%128==0, K%8==0.
template<bool TANH>
__global__ void __launch_bounds__(256)
sgemm128(const float* __restrict__ A, const float* __restrict__ B,
         float* __restrict__ C, int M, int N, int K)
{
    __shared__ float As[8][128];
    __shared__ float Bs[8][128];

    const int tid = threadIdx.x;
    const int rowA0 = blockIdx.y * 128;
    const int colB0 = blockIdx.x * 128;

    // global load mapping
    const int la_r = tid >> 1;          // 0..127
    const int la_c = (tid & 1) * 4;     // 0 or 4
    const int lb_r = tid >> 5;          // 0..7
    const int lb_c = (tid & 31) * 4;    // 0..124

    // compute mapping: 2x2 halves of 4-wide fragments (conflict-free LDS.128)
    const int tx = tid & 15;            // col group
    const int ty = tid >> 4;            // row group

    float acc[8][8];
    #pragma unroll
    for (int i = 0; i < 8; i++)
        #pragma unroll
        for (int j = 0; j < 8; j++) acc[i][j] = 0.f;

    const float* Aptr = A + (size_t)(rowA0 + la_r) * K + la_c;
    const float* Bptr = B + (size_t)lb_r * N + colB0 + lb_c;

    for (int k0 = 0; k0 < K; k0 += 8) {
        float4 av = *(const float4*)Aptr;   Aptr += 8;
        float4 bv = *(const float4*)Bptr;   Bptr += (size_t)8 * N;
        As[la_c + 0][la_r] = av.x;
        As[la_c + 1][la_r] = av.y;
        As[la_c + 2][la_r] = av.z;
        As[la_c + 3][la_r] = av.w;
        *(float4*)&Bs[lb_r][lb_c] = bv;
        __syncthreads();

        #pragma unroll
        for (int k = 0; k < 8; k++) {
            float a[8], b[8];
            *(float4*)&a[0] = *(const float4*)&As[k][ty * 4];
            *(float4*)&a[4] = *(const float4*)&As[k][64 + ty * 4];
            *(float4*)&b[0] = *(const float4*)&Bs[k][tx * 4];
            *(float4*)&b[4] = *(const float4*)&Bs[k][64 + tx * 4];
            #pragma unroll
            for (int i = 0; i < 8; i++)
                #pragma unroll
                for (int j = 0; j < 8; j++)
                    acc[i][j] += a[i] * b[j];
        }
        __syncthreads();
    }

    // epilogue
    #pragma unroll
    for (int ih = 0; ih < 2; ih++) {
        #pragma unroll
        for (int i = 0; i < 4; i++) {
            int row = rowA0 + ih * 64 + ty * 4 + i;
            float* Cr = C + (size_t)row * N + colB0;
            #pragma unroll
            for (int jh = 0; jh < 2; jh++) {
                float4 v;
                float* src = &acc[ih * 4 + i][jh * 4];
                if (TANH) {
                    v.x = tanhf(src[0]); v.y = tanhf(src[1]);
                    v.z = tanhf(src[2]); v.w = tanhf(src[3]);
                } else {
                    v.x = src[0]; v.y = src[1]; v.z = src[2]; v.w = src[3];
                }
                *(float4*)(Cr + jh * 64 + tx * 4) = v;
            }
        }
    }
}

// ---------------- drug branch: Dp[k][m] = LN_over_k(tanh(V @ Hd^T)) ----------------
// one block per drug m; warp-per-k dot products; column LayerNorm over K.
__global__ void __launch_bounds__(256)
drug_branch(const float* __restrict__ V, const float* __restrict__ Hd,
            const float* __restrict__ g, const float* __restrict__ b,
            float* __restrict__ Dp, int K, int d, int M)
{
    __shared__ float sHd[256];
    __shared__ float sT[512];
    __shared__ float red[32];

    const int m = blockIdx.x;
    const int tid = threadIdx.x;

    for (int i = tid; i < d; i += blockDim.x) sHd[i] = Hd[(size_t)m * d + i];
    __syncthreads();

    const int warp = tid >> 5, lane = tid & 31;
    const int nwarp = blockDim.x >> 5;
    for (int k = warp; k < K; k += nwarp) {
        const float* vr = V + (size_t)k * d;
        float p = 0.f;
        for (int dd = lane; dd < d; dd += 32) p += vr[dd] * sHd[dd];
        #pragma unroll
        for (int o = 16; o; o >>= 1) p += __shfl_xor_sync(0xffffffffu, p, o);
        if (lane == 0) sT[k] = tanhf(p);
    }
    __syncthreads();

    float s = 0.f, s2 = 0.f;
    for (int k = tid; k < K; k += blockDim.x) { float v = sT[k]; s += v; s2 += v * v; }
    s  = blockReduceSum(s,  red);
    s2 = blockReduceSum(s2, red);
    float mu = s / (float)K;
    float rstd = rsqrtf(s2 / (float)K - mu * mu + LN_EPS);

    for (int k = tid; k < K; k += blockDim.x)
        Dp[(size_t)k * M + m] = (sT[k] - mu) * rstd * g[k] + b[k];
}

// ---------------- row LayerNorm of A (in place), then * q ----------------
__global__ void __launch_bounds__(128)
ln_rows(float* __restrict__ A, const float* __restrict__ g,
        const float* __restrict__ b, const float* __restrict__ q, int K)
{
    __shared__ float red[32];
    float* Ar = A + (size_t)blockIdx.x * K;
    float s = 0.f, s2 = 0.f;
    for (int k = threadIdx.x; k < K; k += blockDim.x) {
        float v = Ar[k]; s += v; s2 += v * v;
    }
    s  = blockReduceSum(s,  red);
    s2 = blockReduceSum(s2, red);
    float mu = s / (float)K;
    float rstd = rsqrtf(s2 / (float)K - mu * mu + LN_EPS);
    for (int k = threadIdx.x; k < K; k += blockDim.x) {
        float v = Ar[k];
        Ar[k] = ((v - mu) * rstd * g[k] + b[k]) * q[k];
    }
}

// ---------------- row softmax of S (in place) ----------------
// requires M % blockDim.x == 0 and M/blockDim.x <= 8
__global__ void __launch_bounds__(256)
softmax_rows(float* __restrict__ S, int M)
{
    __shared__ float red[32];
    float* Sr = S + (size_t)blockIdx.x * M;
    const int nit = M / blockDim.x;
    float v[8];
    float mx = -INFINITY;
    for (int i = 0; i < nit; i++) {
        v[i] = Sr[threadIdx.x + i * blockDim.x];
        mx = fmaxf(mx, v[i]);
    }
    mx = blockReduceMax(mx, red);
    float s = 0.f;
    for (int i = 0; i < nit; i++) { v[i] = expf(v[i] - mx); s += v[i]; }
    s = blockReduceSum(s, red);
    float inv = 1.f / s;
    for (int i = 0; i < nit; i++) Sr[threadIdx.x + i * blockDim.x] = v[i] * inv;
}

// ---------------- launch ----------------
extern "C" void kernel_launch(void* const* d_in, const int* in_sizes, int n_in,
                              void* d_out, int out_size)
{
    const float* H_rna  = (const float*)d_in[0];
    const float* H_drug = (const float*)d_in[1];
    const float* U      = (const float*)d_in[2];
    const float* V      = (const float*)d_in[3];
    const float* q      = (const float*)d_in[4];
    const float* g_rna  = (const float*)d_in[5];
    const float* b_rna  = (const float*)d_in[6];
    const float* g_drug = (const float*)d_in[7];
    const float* b_drug = (const float*)d_in[8];

    const int K = in_sizes[4];             // 512
    const int d = in_sizes[2] / K;         // 256
    const int N = in_sizes[0] / d;         // 65536
    const int M = in_sizes[1] / d;         // 2048

    float *pA, *pS, *pDp;
    cudaGetSymbolAddress((void**)&pA,  g_A);
    cudaGetSymbolAddress((void**)&pS,  g_S);
    cudaGetSymbolAddress((void**)&pDp, g_Dp);

    // 1) Dp = LN_cols(tanh(V @ Hd^T))  -> [K, M]
    drug_branch<<<M, 256>>>(V, H_drug, g_drug, b_drug, pDp, K, d, M);

    // 2) A = tanh(H_rna @ U)           -> [N, K]
    {
        dim3 grid(K / 128, N / 128);
        sgemm128<true><<<grid, 256>>>(H_rna, U, pA, N, K, d);
    }

    // 3) A = LN_rows(A) * q            (in place)
    ln_rows<<<N, 128>>>(pA, g_rna, b_rna, q, K);

    // 4) S = A @ Dp                    -> [N, M]
    {
        dim3 grid(M / 128, N / 128);
        sgemm128<false><<<grid, 256>>>(pA, pDp, pS, N, M, K);
    }

    // 5) P = softmax_rows(S)           (in place)
    softmax_rows<<<N, 256>>>(pS, M);

    // 6) out = P @ H_drug              -> [N, d]
    {
        dim3 grid(d / 128, N / 128);
        sgemm128<false><<<grid, 256>>>(pS, H_drug, (float*)d_out, N, d, M);
    }
}

// round 5
// speedup vs baseline: 2.0253x; 2.0253x over previous
#include <cuda_runtime.h>
#include <cuda_fp16.h>
#include <cstdint>
#include <math.h>

// Fixed shapes (registry): N=65536, M=2048, d=256, K=512
#define NN 65536
#define MM 2048
#define DD 256
#define KK 512
#define LN_EPS 1e-5f

// ---------------- static scratch (no allocations allowed) ----------------
__device__ __align__(256) float  g_A   [(size_t)NN * KK];  // 128MB tanh(H@U) fp32
__device__ __align__(256) float  g_S   [(size_t)NN * MM];  // 512MB scores fp32
__device__ __align__(256) __half g_Ahi [(size_t)NN * KK];
__device__ __align__(256) __half g_Alo [(size_t)NN * KK];
__device__ __align__(256) __half g_Phi [(size_t)NN * MM];
__device__ __align__(256) __half g_Plo [(size_t)NN * MM];
__device__ __align__(256) __half g_Hrhi[(size_t)NN * DD];
__device__ __align__(256) __half g_Hrlo[(size_t)NN * DD];
__device__ __align__(256) __half g_DpThi[(size_t)MM * KK];
__device__ __align__(256) __half g_DpTlo[(size_t)MM * KK];
__device__ __align__(256) __half g_HdThi[(size_t)DD * MM];
__device__ __align__(256) __half g_HdTlo[(size_t)DD * MM];
__device__ __align__(256) __half g_Uthi [(size_t)KK * DD];
__device__ __align__(256) __half g_Utlo [(size_t)KK * DD];

// ---------------- helpers ----------------
__device__ __forceinline__ uint32_t smem_u32(const void* p) {
    uint32_t a;
    asm("{ .reg .u64 t; cvta.to.shared.u64 t, %1; cvt.u32.u64 %0, t; }" : "=r"(a) : "l"(p));
    return a;
}
__device__ __forceinline__ void cp16(uint32_t dst, const void* src) {
    asm volatile("cp.async.cg.shared.global [%0], [%1], 16;" :: "r"(dst), "l"(src));
}
#define CP_COMMIT()  asm volatile("cp.async.commit_group;" ::: "memory")
#define CP_WAIT0()   asm volatile("cp.async.wait_group 0;"  ::: "memory")
#define CP_WAIT1()   asm volatile("cp.async.wait_group 1;"  ::: "memory")

#define LDSM4(r, addr) \
    asm volatile("ldmatrix.sync.aligned.m8n8.x4.shared.b16 {%0,%1,%2,%3}, [%4];" \
        : "=r"((r)[0]), "=r"((r)[1]), "=r"((r)[2]), "=r"((r)[3]) : "r"(addr))

#define MMA16816(c, a, b0, b1) \
    asm volatile("mma.sync.aligned.m16n8k16.row.col.f32.f16.f16.f32 " \
        "{%0,%1,%2,%3}, {%4,%5,%6,%7}, {%8,%9}, {%0,%1,%2,%3};" \
        : "+f"((c)[0]), "+f"((c)[1]), "+f"((c)[2]), "+f"((c)[3]) \
        : "r"((a)[0]), "r"((a)[1]), "r"((a)[2]), "r"((a)[3]), "r"(b0), "r"(b1))

__device__ __forceinline__ void split2h(float x, __half& h, __half& l) {
    h = __float2half(x);
    l = __float2half(x - __half2float(h));
}

// ---------------- block reduce helpers ----------------
__device__ __forceinline__ float blockReduceSum(float v, volatile float* sm) {
    int lane = threadIdx.x & 31, w = threadIdx.x >> 5;
    #pragma unroll
    for (int o = 16; o; o >>= 1) v += __shfl_xor_sync(0xffffffffu, v, o);
    __syncthreads();
    if (lane == 0) sm[w] = v;
    __syncthreads();
    if (w == 0) {
        float x = (lane < (int)(blockDim.x >> 5)) ? sm[lane] : 0.f;
        #pragma unroll
        for (int o = 16; o; o >>= 1) x += __shfl_xor_sync(0xffffffffu, x, o);
        if (lane == 0) sm[0] = x;
    }
    __syncthreads();
    float r = sm[0];
    __syncthreads();
    return r;
}
__device__ __forceinline__ float blockReduceMax(float v, volatile float* sm) {
    int lane = threadIdx.x & 31, w = threadIdx.x >> 5;
    #pragma unroll
    for (int o = 16; o; o >>= 1) v = fmaxf(v, __shfl_xor_sync(0xffffffffu, v, o));
    __syncthreads();
    if (lane == 0) sm[w] = v;
    __syncthreads();
    if (w == 0) {
        float x = (lane < (int)(blockDim.x >> 5)) ? sm[lane] : -INFINITY;
        #pragma unroll
        for (int o = 16; o; o >>= 1) x = fmaxf(x, __shfl_xor_sync(0xffffffffu, x, o));
        if (lane == 0) sm[0] = x;
    }
    __syncthreads();
    float r = sm[0];
    __syncthreads();
    return r;
}

// ============ HMMA GEMM: C[rows,Ncols] = A[rows,Ktot] @ B[Ncols,Ktot]^T ============
// A,B as (hi,lo) fp16 splits; 3 products (hh + hl + lh) in fp32 accumulators.
// CTA tile 128x128, BK=32, double-buffered cp.async, 8 warps (4x2).
// SMEM row layout per matrix: 128 rows x 128B (hi: bytes 0..63, lo: 64..127), SW128.
// EPI: 0 = none, 1 = tanh
template<int EPI>
__global__ void __launch_bounds__(256)
gemm_hmma(const __half* __restrict__ Ahi, const __half* __restrict__ Alo,
          const __half* __restrict__ Bhi, const __half* __restrict__ Blo,
          float* __restrict__ C, int Ktot, int Ncols)
{
    extern __shared__ char smem[];
    const int tid  = threadIdx.x;
    const int wid  = tid >> 5, lane = tid & 31;
    const int row0 = blockIdx.y * 128;
    const int col0 = blockIdx.x * 128;
    const int nch  = Ktot >> 5;          // K-chunks of 32

    // buffers: [A0 16K][B0 16K][A1 16K][B1 16K]
    const uint32_t sb = smem_u32(smem);
    uint32_t Ab[2] = { sb,          sb + 32768 };
    uint32_t Bb[2] = { sb + 16384,  sb + 49152 };

    const int wr = wid >> 1;   // warp row block (x32)
    const int wc = wid & 1;    // warp col block (x64)

    float acc[2][8][4];
    #pragma unroll
    for (int i = 0; i < 2; i++)
        #pragma unroll
        for (int j = 0; j < 8; j++)
            #pragma unroll
            for (int k = 0; k < 4; k++) acc[i][j][k] = 0.f;

    const int lm = lane >> 3;   // ldmatrix sub-matrix id
    const int lr = lane & 7;

    auto load_chunk = [&](int ch, int buf) {
        const int kc0 = ch << 5;
        #pragma unroll
        for (int g = tid; g < 2048; g += 256) {
            int mat = g >> 10;            // 0:A 1:B
            int r   = (g >> 3) & 127;
            int s   = g & 7;              // 8 x 16B segments per row
            int split = s >> 2;           // 0:hi 1:lo
            int seg   = s & 3;
            const __half* srcb;
            int grow;
            if (mat == 0) { srcb = split ? Alo : Ahi; grow = row0 + r; }
            else          { srcb = split ? Blo : Bhi; grow = col0 + r; }
            const __half* src = srcb + (size_t)grow * Ktot + kc0 + seg * 8;
            uint32_t off = (uint32_t)(r * 128 + split * 64 + seg * 16);
            uint32_t dst = (mat ? Bb[buf] : Ab[buf]) + (off ^ ((off >> 3) & 0x70));
            cp16(dst, src);
        }
        CP_COMMIT();
    };

    auto compute = [&](int buf) {
        #pragma unroll
        for (int p = 0; p < 3; p++) {
            const int aoff = (p == 2) ? 64 : 0;   // product 2 uses A-lo
            const int boff = (p == 1) ? 64 : 0;   // product 1 uses B-lo
            #pragma unroll
            for (int ks = 0; ks < 2; ks++) {
                uint32_t a[2][4];
                #pragma unroll
                for (int mt = 0; mt < 2; mt++) {
                    int r = wr * 32 + mt * 16 + (lm & 1) * 8 + lr;
                    int c = aoff + ks * 32 + (lm >> 1) * 16;
                    uint32_t addr = Ab[buf] + (uint32_t)(r * 128) + (uint32_t)(c ^ ((r & 7) << 4));
                    LDSM4(a[mt], addr);
                }
                uint32_t b[4][4];
                #pragma unroll
                for (int nt2 = 0; nt2 < 4; nt2++) {
                    int r = wc * 64 + nt2 * 16 + (lm >> 1) * 8 + lr;
                    int c = boff + ks * 32 + (lm & 1) * 16;
                    uint32_t addr = Bb[buf] + (uint32_t)(r * 128) + (uint32_t)(c ^ ((r & 7) << 4));
                    LDSM4(b[nt2], addr);
                }
                #pragma unroll
                for (int mt = 0; mt < 2; mt++)
                    #pragma unroll
                    for (int nt = 0; nt < 8; nt++)
                        MMA16816(acc[mt][nt], a[mt],
                                 b[nt >> 1][(nt & 1) * 2], b[nt >> 1][(nt & 1) * 2 + 1]);
            }
        }
    };

    load_chunk(0, 0);
    for (int i = 0; i < nch; i++) {
        if (i + 1 < nch) { load_chunk(i + 1, (i + 1) & 1); CP_WAIT1(); }
        else             { CP_WAIT0(); }
        __syncthreads();
        compute(i & 1);
        __syncthreads();
    }

    // epilogue: mma C layout -> gmem (float2 stores)
    #pragma unroll
    for (int mt = 0; mt < 2; mt++) {
        #pragma unroll
        for (int nt = 0; nt < 8; nt++) {
            int r = row0 + wr * 32 + mt * 16 + (lane >> 2);
            int c = col0 + wc * 64 + nt * 8 + (lane & 3) * 2;
            float2 v0 = make_float2(acc[mt][nt][0], acc[mt][nt][1]);
            float2 v1 = make_float2(acc[mt][nt][2], acc[mt][nt][3]);
            if (EPI == 1) {
                v0.x = tanhf(v0.x); v0.y = tanhf(v0.y);
                v1.x = tanhf(v1.x); v1.y = tanhf(v1.y);
            }
            *(float2*)&C[(size_t)r * Ncols + c]       = v0;
            *(float2*)&C[(size_t)(r + 8) * Ncols + c] = v1;
        }
    }
}

// ---------------- prep kernels ----------------
__global__ void split_kernel(const float* __restrict__ in,
                             __half* __restrict__ hi, __half* __restrict__ lo, size_t n)
{
    for (size_t i = (size_t)blockIdx.x * blockDim.x + threadIdx.x; i < n;
         i += (size_t)gridDim.x * blockDim.x) {
        __half h, l; split2h(in[i], h, l);
        hi[i] = h; lo[i] = l;
    }
}

__global__ void tsplit_kernel(const float* __restrict__ in,
                              __half* __restrict__ hiT, __half* __restrict__ loT,
                              int R, int C)
{
    int idx = blockIdx.x * blockDim.x + threadIdx.x;
    if (idx < R * C) {
        int r = idx / C, c = idx % C;
        __half h, l; split2h(in[idx], h, l);
        hiT[(size_t)c * R + r] = h;
        loT[(size_t)c * R + r] = l;
    }
}

// ---------------- drug branch: DpT[m,k] = LN_k(tanh(V@Hd^T)), fp16 splits ----------------
__global__ void __launch_bounds__(256)
drug_branch(const float* __restrict__ V, const float* __restrict__ Hd,
            const float* __restrict__ g, const float* __restrict__ b,
            __half* __restrict__ DpThi, __half* __restrict__ DpTlo,
            int K, int d, int M)
{
    __shared__ float sHd[DD];
    __shared__ float sT[KK];
    __shared__ float red[32];
    const int m = blockIdx.x;
    const int tid = threadIdx.x;

    for (int i = tid; i < d; i += blockDim.x) sHd[i] = Hd[(size_t)m * d + i];
    __syncthreads();

    const int warp = tid >> 5, lane = tid & 31, nwarp = blockDim.x >> 5;
    for (int k = warp; k < K; k += nwarp) {
        const float* vr = V + (size_t)k * d;
        float p = 0.f;
        for (int dd2 = lane; dd2 < d; dd2 += 32) p += vr[dd2] * sHd[dd2];
        #pragma unroll
        for (int o = 16; o; o >>= 1) p += __shfl_xor_sync(0xffffffffu, p, o);
        if (lane == 0) sT[k] = tanhf(p);
    }
    __syncthreads();

    float s = 0.f, s2 = 0.f;
    for (int k = tid; k < K; k += blockDim.x) { float v = sT[k]; s += v; s2 += v * v; }
    s  = blockReduceSum(s,  red);
    s2 = blockReduceSum(s2, red);
    float mu = s / (float)K;
    float rstd = rsqrtf(s2 / (float)K - mu * mu + LN_EPS);

    for (int k = tid; k < K; k += blockDim.x) {
        float y = (sT[k] - mu) * rstd * g[k] + b[k];
        __half h, l; split2h(y, h, l);
        DpThi[(size_t)m * K + k] = h;
        DpTlo[(size_t)m * K + k] = l;
    }
}

// ---------------- row LayerNorm of A, *q, fp16 splits ----------------
__global__ void __launch_bounds__(128)
ln_rows(const float* __restrict__ A, const float* __restrict__ g,
        const float* __restrict__ b, const float* __restrict__ q,
        __half* __restrict__ Ahi, __half* __restrict__ Alo, int K)
{
    __shared__ float red[32];
    const float* Ar = A + (size_t)blockIdx.x * K;
    float s = 0.f, s2 = 0.f;
    for (int k = threadIdx.x; k < K; k += blockDim.x) {
        float v = Ar[k]; s += v; s2 += v * v;
    }
    s  = blockReduceSum(s,  red);
    s2 = blockReduceSum(s2, red);
    float mu = s / (float)K;
    float rstd = rsqrtf(s2 / (float)K - mu * mu + LN_EPS);
    for (int k = threadIdx.x; k < K; k += blockDim.x) {
        float y = ((Ar[k] - mu) * rstd * g[k] + b[k]) * q[k];
        __half h, l; split2h(y, h, l);
        Ahi[(size_t)blockIdx.x * K + k] = h;
        Alo[(size_t)blockIdx.x * K + k] = l;
    }
}

// ---------------- row softmax of S, fp16 splits ----------------
__global__ void __launch_bounds__(256)
softmax_rows(const float* __restrict__ S,
             __half* __restrict__ Phi, __half* __restrict__ Plo, int M)
{
    __shared__ float red[32];
    const float* Sr = S + (size_t)blockIdx.x * M;
    const int nit = M / 256;
    float v[8];
    float mx = -INFINITY;
    for (int i = 0; i < nit; i++) {
        v[i] = Sr[threadIdx.x + i * 256];
        mx = fmaxf(mx, v[i]);
    }
    mx = blockReduceMax(mx, red);
    float s = 0.f;
    for (int i = 0; i < nit; i++) { v[i] = expf(v[i] - mx); s += v[i]; }
    s = blockReduceSum(s, red);
    float inv = 1.f / s;
    for (int i = 0; i < nit; i++) {
        float p = v[i] * inv;
        __half h, l; split2h(p, h, l);
        size_t o = (size_t)blockIdx.x * M + threadIdx.x + i * 256;
        Phi[o] = h; Plo[o] = l;
    }
}

// ---------------- launch ----------------
extern "C" void kernel_launch(void* const* d_in, const int* in_sizes, int n_in,
                              void* d_out, int out_size)
{
    const float* H_rna  = (const float*)d_in[0];
    const float* H_drug = (const float*)d_in[1];
    const float* U      = (const float*)d_in[2];
    const float* V      = (const float*)d_in[3];
    const float* q      = (const float*)d_in[4];
    const float* g_rna  = (const float*)d_in[5];
    const float* b_rna  = (const float*)d_in[6];
    const float* g_drug = (const float*)d_in[7];
    const float* b_drug = (const float*)d_in[8];

    const int K = in_sizes[4];             // 512
    const int d = in_sizes[2] / K;         // 256
    const int N = in_sizes[0] / d;         // 65536
    const int M = in_sizes[1] / d;         // 2048

    float *pA, *pS;
    __half *pAhi, *pAlo, *pPhi, *pPlo, *pHrhi, *pHrlo;
    __half *pDpThi, *pDpTlo, *pHdThi, *pHdTlo, *pUthi, *pUtlo;
    cudaGetSymbolAddress((void**)&pA,     g_A);
    cudaGetSymbolAddress((void**)&pS,     g_S);
    cudaGetSymbolAddress((void**)&pAhi,   g_Ahi);
    cudaGetSymbolAddress((void**)&pAlo,   g_Alo);
    cudaGetSymbolAddress((void**)&pPhi,   g_Phi);
    cudaGetSymbolAddress((void**)&pPlo,   g_Plo);
    cudaGetSymbolAddress((void**)&pHrhi,  g_Hrhi);
    cudaGetSymbolAddress((void**)&pHrlo,  g_Hrlo);
    cudaGetSymbolAddress((void**)&pDpThi, g_DpThi);
    cudaGetSymbolAddress((void**)&pDpTlo, g_DpTlo);
    cudaGetSymbolAddress((void**)&pHdThi, g_HdThi);
    cudaGetSymbolAddress((void**)&pHdTlo, g_HdTlo);
    cudaGetSymbolAddress((void**)&pUthi,  g_Uthi);
    cudaGetSymbolAddress((void**)&pUtlo,  g_Utlo);

    const int SMEMSZ = 65536;
    cudaFuncSetAttribute(gemm_hmma<0>, cudaFuncAttributeMaxDynamicSharedMemorySize, SMEMSZ);
    cudaFuncSetAttribute(gemm_hmma<1>, cudaFuncAttributeMaxDynamicSharedMemorySize, SMEMSZ);

    // prep: splits / transposes
    split_kernel<<<4096, 256>>>(H_rna, pHrhi, pHrlo, (size_t)N * d);
    tsplit_kernel<<<(d * K + 255) / 256, 256>>>(U, pUthi, pUtlo, d, K);        // U[d,K] -> Ut[K,d]
    tsplit_kernel<<<(M * d + 255) / 256, 256>>>(H_drug, pHdThi, pHdTlo, M, d); // Hd[M,d] -> HdT[d,M]

    // 1) DpT = LN_cols(tanh(V @ Hd^T)) -> [M, K] fp16 splits
    drug_branch<<<M, 256>>>(V, H_drug, g_drug, b_drug, pDpThi, pDpTlo, K, d, M);

    // 2) A = tanh(H_rna @ U) -> fp32 [N, K]
    gemm_hmma<1><<<dim3(K / 128, N / 128), 256, SMEMSZ>>>(pHrhi, pHrlo, pUthi, pUtlo, pA, d, K);

    // 3) LN rows + *q -> fp16 splits
    ln_rows<<<N, 128>>>(pA, g_rna, b_rna, q, pAhi, pAlo, K);

    // 4) S = A @ Dp -> fp32 [N, M]
    gemm_hmma<0><<<dim3(M / 128, N / 128), 256, SMEMSZ>>>(pAhi, pAlo, pDpThi, pDpTlo, pS, K, M);

    // 5) P = softmax rows -> fp16 splits
    softmax_rows<<<N, 256>>>(pS, pPhi, pPlo, M);

    // 6) out = P @ H_drug -> fp32 [N, d]
    gemm_hmma<0><<<dim3(d / 128, N / 128), 256, SMEMSZ>>>(pPhi, pPlo, pHdThi, pHdTlo, (float*)d_out, M, d);
}

// round 7
// speedup vs baseline: 2.4935x; 1.2312x over previous
#include <cuda_runtime.h>
#include <cuda_fp16.h>
#include <cstdint>
#include <math.h>

// Fixed shapes (registry): N=65536, M=2048, d=256, K=512
#define NN 65536
#define MM 2048
#define DD 256
#define KK 512
#define LN_EPS 1e-5f

// ---------------- static scratch (no allocations allowed) ----------------
__device__ __align__(256) float  g_A   [(size_t)NN * KK];  // 128MB tanh(H@U) fp32
__device__ __align__(256) float  g_S   [(size_t)NN * MM];  // 512MB scores fp32
__device__ __align__(256) float  g_T   [(size_t)MM * KK];  //   4MB tanh(Hd@V^T) fp32
__device__ __align__(256) __half g_Ahi [(size_t)NN * KK];
__device__ __align__(256) __half g_Alo [(size_t)NN * KK];
__device__ __align__(256) __half g_Phi [(size_t)NN * MM];
__device__ __align__(256) __half g_Plo [(size_t)NN * MM];
__device__ __align__(256) __half g_Hrhi[(size_t)NN * DD];
__device__ __align__(256) __half g_Hrlo[(size_t)NN * DD];
__device__ __align__(256) __half g_Hdhi[(size_t)MM * DD];
__device__ __align__(256) __half g_Hdlo[(size_t)MM * DD];
__device__ __align__(256) __half g_Vhi [(size_t)KK * DD];
__device__ __align__(256) __half g_Vlo [(size_t)KK * DD];
__device__ __align__(256) __half g_DpThi[(size_t)MM * KK];
__device__ __align__(256) __half g_DpTlo[(size_t)MM * KK];
__device__ __align__(256) __half g_HdThi[(size_t)DD * MM];
__device__ __align__(256) __half g_HdTlo[(size_t)DD * MM];
__device__ __align__(256) __half g_Uthi [(size_t)KK * DD];
__device__ __align__(256) __half g_Utlo [(size_t)KK * DD];

// ---------------- helpers ----------------
__device__ __forceinline__ uint32_t smem_u32(const void* p) {
    uint32_t a;
    asm("{ .reg .u64 t; cvta.to.shared.u64 t, %1; cvt.u32.u64 %0, t; }" : "=r"(a) : "l"(p));
    return a;
}
__device__ __forceinline__ void cp16(uint32_t dst, const void* src) {
    asm volatile("cp.async.cg.shared.global [%0], [%1], 16;" :: "r"(dst), "l"(src));
}
#define CP_COMMIT()  asm volatile("cp.async.commit_group;" ::: "memory")
#define CP_WAIT0()   asm volatile("cp.async.wait_group 0;"  ::: "memory")
#define CP_WAIT1()   asm volatile("cp.async.wait_group 1;"  ::: "memory")

#define LDSM4(r, addr) \
    asm volatile("ldmatrix.sync.aligned.m8n8.x4.shared.b16 {%0,%1,%2,%3}, [%4];" \
        : "=r"((r)[0]), "=r"((r)[1]), "=r"((r)[2]), "=r"((r)[3]) : "r"(addr))

#define MMA16816(c, a, b0, b1) \
    asm volatile("mma.sync.aligned.m16n8k16.row.col.f32.f16.f16.f32 " \
        "{%0,%1,%2,%3}, {%4,%5,%6,%7}, {%8,%9}, {%0,%1,%2,%3};" \
        : "+f"((c)[0]), "+f"((c)[1]), "+f"((c)[2]), "+f"((c)[3]) \
        : "r"((a)[0]), "r"((a)[1]), "r"((a)[2]), "r"((a)[3]), "r"(b0), "r"(b1))

__device__ __forceinline__ void split2h(float x, __half& h, __half& l) {
    h = __float2half(x);
    l = __float2half(x - __half2float(h));
}

// ---------------- block reduce helpers ----------------
__device__ __forceinline__ float blockReduceSum(float v, volatile float* sm) {
    int lane = threadIdx.x & 31, w = threadIdx.x >> 5;
    #pragma unroll
    for (int o = 16; o; o >>= 1) v += __shfl_xor_sync(0xffffffffu, v, o);
    __syncthreads();
    if (lane == 0) sm[w] = v;
    __syncthreads();
    if (w == 0) {
        float x = (lane < (int)(blockDim.x >> 5)) ? sm[lane] : 0.f;
        #pragma unroll
        for (int o = 16; o; o >>= 1) x += __shfl_xor_sync(0xffffffffu, x, o);
        if (lane == 0) sm[0] = x;
    }
    __syncthreads();
    float r = sm[0];
    __syncthreads();
    return r;
}
__device__ __forceinline__ float blockReduceMax(float v, volatile float* sm) {
    int lane = threadIdx.x & 31, w = threadIdx.x >> 5;
    #pragma unroll
    for (int o = 16; o; o >>= 1) v = fmaxf(v, __shfl_xor_sync(0xffffffffu, v, o));
    __syncthreads();
    if (lane == 0) sm[w] = v;
    __syncthreads();
    if (w == 0) {
        float x = (lane < (int)(blockDim.x >> 5)) ? sm[lane] : -INFINITY;
        #pragma unroll
        for (int o = 16; o; o >>= 1) x = fmaxf(x, __shfl_xor_sync(0xffffffffu, x, o));
        if (lane == 0) sm[0] = x;
    }
    __syncthreads();
    float r = sm[0];
    __syncthreads();
    return r;
}

// ============ HMMA GEMM: C[rows,Ncols] = A[rows,Ktot] @ B[Ncols,Ktot]^T ============
// A,B as (hi,lo) fp16 splits; 3 products (hh + lh + hl) in fp32 accumulators.
// CTA tile 128x128, BK=32, 3-stage cp.async ring (one __syncthreads per chunk),
// 8 warps (4x2), 2 CTAs/SM.
// SMEM row layout per matrix: 128 rows x 128B (hi: bytes 0..63, lo: 64..127), SW128.
// EPI: 0 = none, 1 = tanh
template<int EPI>
__global__ void __launch_bounds__(256, 2)
gemm_hmma(const __half* __restrict__ Ahi, const __half* __restrict__ Alo,
          const __half* __restrict__ Bhi, const __half* __restrict__ Blo,
          float* __restrict__ C, int Ktot, int Ncols)
{
    extern __shared__ char smem[];
    const int tid  = threadIdx.x;
    const int wid  = tid >> 5, lane = tid & 31;
    const int row0 = blockIdx.y * 128;
    const int col0 = blockIdx.x * 128;
    const int nch  = Ktot >> 5;          // K-chunks of 32

    const uint32_t sb = smem_u32(smem);  // 3 stages x (A 16KB + B 16KB)

    const int wr = wid >> 1;   // warp row block (x32)
    const int wc = wid & 1;    // warp col block (x64)
    const int lm = lane >> 3;  // ldmatrix sub-matrix id
    const int lr = lane & 7;

    float acc[2][8][4];
    #pragma unroll
    for (int i = 0; i < 2; i++)
        #pragma unroll
        for (int j = 0; j < 8; j++)
            #pragma unroll
            for (int k = 0; k < 4; k++) acc[i][j][k] = 0.f;

    auto load_chunk = [&](int ch, int stage) {
        const int kc0 = ch << 5;
        const uint32_t Ab = sb + (uint32_t)stage * 32768u;
        const uint32_t Bb = Ab + 16384u;
        #pragma unroll
        for (int g = tid; g < 2048; g += 256) {
            int mat = g >> 10;            // 0:A 1:B
            int r   = (g >> 3) & 127;
            int s   = g & 7;              // 8 x 16B segments per row
            int split = s >> 2;           // 0:hi 1:lo
            int seg   = s & 3;
            const __half* srcb;
            int grow;
            if (mat == 0) { srcb = split ? Alo : Ahi; grow = row0 + r; }
            else          { srcb = split ? Blo : Bhi; grow = col0 + r; }
            const __half* src = srcb + (size_t)grow * Ktot + kc0 + seg * 8;
            uint32_t off = (uint32_t)(r * 128 + split * 64 + seg * 16);
            uint32_t dst = (mat ? Bb : Ab) + (off ^ ((off >> 3) & 0x70));
            cp16(dst, src);
        }
        CP_COMMIT();
    };

    auto compute = [&](int stage) {
        const uint32_t Ab = sb + (uint32_t)stage * 32768u;
        const uint32_t Bb = Ab + 16384u;
        #pragma unroll
        for (int ks = 0; ks < 2; ks++) {
            // A fragments: hi and lo (16 rows x 16 cols each, 2 row-tiles)
            uint32_t ah[2][4], al[2][4];
            #pragma unroll
            for (int mt = 0; mt < 2; mt++) {
                int r = wr * 32 + mt * 16 + (lm & 1) * 8 + lr;
                int ch = ks * 32 + (lm >> 1) * 16;
                uint32_t rowa = Ab + (uint32_t)(r * 128);
                LDSM4(ah[mt], rowa + (uint32_t)( ch       ^ ((r & 7) << 4)));
                LDSM4(al[mt], rowa + (uint32_t)((ch + 64) ^ ((r & 7) << 4)));
            }
            // B hi fragments
            uint32_t b[4][4];
            #pragma unroll
            for (int nt2 = 0; nt2 < 4; nt2++) {
                int r = wc * 64 + nt2 * 16 + (lm >> 1) * 8 + lr;
                int cb = ks * 32 + (lm & 1) * 16;
                LDSM4(b[nt2], Bb + (uint32_t)(r * 128) + (uint32_t)(cb ^ ((r & 7) << 4)));
            }
            // hh
            #pragma unroll
            for (int mt = 0; mt < 2; mt++)
                #pragma unroll
                for (int nt = 0; nt < 8; nt++)
                    MMA16816(acc[mt][nt], ah[mt],
                             b[nt >> 1][(nt & 1) * 2], b[nt >> 1][(nt & 1) * 2 + 1]);
            // lh (A-lo x B-hi, reuse b regs)
            #pragma unroll
            for (int mt = 0; mt < 2; mt++)
                #pragma unroll
                for (int nt = 0; nt < 8; nt++)
                    MMA16816(acc[mt][nt], al[mt],
                             b[nt >> 1][(nt & 1) * 2], b[nt >> 1][(nt & 1) * 2 + 1]);
            // B lo fragments (overwrite b)
            #pragma unroll
            for (int nt2 = 0; nt2 < 4; nt2++) {
                int r = wc * 64 + nt2 * 16 + (lm >> 1) * 8 + lr;
                int cb = 64 + ks * 32 + (lm & 1) * 16;
                LDSM4(b[nt2], Bb + (uint32_t)(r * 128) + (uint32_t)(cb ^ ((r & 7) << 4)));
            }
            // hl
            #pragma unroll
            for (int mt = 0; mt < 2; mt++)
                #pragma unroll
                for (int nt = 0; nt < 8; nt++)
                    MMA16816(acc[mt][nt], ah[mt],
                             b[nt >> 1][(nt & 1) * 2], b[nt >> 1][(nt & 1) * 2 + 1]);
        }
    };

    load_chunk(0, 0);
    load_chunk(1, 1);
    for (int i = 0; i < nch; i++) {
        if (i + 1 < nch) CP_WAIT1(); else CP_WAIT0();
        __syncthreads();
        if (i + 2 < nch) {
            int st = i + 2; st -= (st / 3) * 3;      // (i+2) % 3
            load_chunk(i + 2, st);
        }
        int cs = i; cs -= (cs / 3) * 3;              // i % 3
        compute(cs);
    }

    // epilogue: mma C layout -> gmem (float2 stores)
    #pragma unroll
    for (int mt = 0; mt < 2; mt++) {
        #pragma unroll
        for (int nt = 0; nt < 8; nt++) {
            int r = row0 + wr * 32 + mt * 16 + (lane >> 2);
            int c = col0 + wc * 64 + nt * 8 + (lane & 3) * 2;
            float2 v0 = make_float2(acc[mt][nt][0], acc[mt][nt][1]);
            float2 v1 = make_float2(acc[mt][nt][2], acc[mt][nt][3]);
            if (EPI == 1) {
                v0.x = tanhf(v0.x); v0.y = tanhf(v0.y);
                v1.x = tanhf(v1.x); v1.y = tanhf(v1.y);
            }
            *(float2*)&C[(size_t)r * Ncols + c]       = v0;
            *(float2*)&C[(size_t)(r + 8) * Ncols + c] = v1;
        }
    }
}

// ---------------- prep kernels ----------------
__global__ void split_kernel(const float* __restrict__ in,
                             __half* __restrict__ hi, __half* __restrict__ lo, size_t n)
{
    for (size_t i = (size_t)blockIdx.x * blockDim.x + threadIdx.x; i < n;
         i += (size_t)gridDim.x * blockDim.x) {
        __half h, l; split2h(in[i], h, l);
        hi[i] = h; lo[i] = l;
    }
}

__global__ void tsplit_kernel(const float* __restrict__ in,
                              __half* __restrict__ hiT, __half* __restrict__ loT,
                              int R, int C)
{
    int idx = blockIdx.x * blockDim.x + threadIdx.x;
    if (idx < R * C) {
        int r = idx / C, c = idx % C;
        __half h, l; split2h(in[idx], h, l);
        hiT[(size_t)c * R + r] = h;
        loT[(size_t)c * R + r] = l;
    }
}

// ---------------- row LayerNorm (+ optional *q), fp16 split outputs ----------------
template<bool QMUL>
__global__ void __launch_bounds__(128)
ln_rows(const float* __restrict__ A, const float* __restrict__ g,
        const float* __restrict__ b, const float* __restrict__ q,
        __half* __restrict__ Ohi, __half* __restrict__ Olo, int K)
{
    __shared__ float red[32];
    const float* Ar = A + (size_t)blockIdx.x * K;
    float s = 0.f, s2 = 0.f;
    for (int k = threadIdx.x; k < K; k += blockDim.x) {
        float v = Ar[k]; s += v; s2 += v * v;
    }
    s  = blockReduceSum(s,  red);
    s2 = blockReduceSum(s2, red);
    float mu = s / (float)K;
    float rstd = rsqrtf(s2 / (float)K - mu * mu + LN_EPS);
    for (int k = threadIdx.x; k < K; k += blockDim.x) {
        float y = (Ar[k] - mu) * rstd * g[k] + b[k];
        if (QMUL) y *= q[k];
        __half h, l; split2h(y, h, l);
        Ohi[(size_t)blockIdx.x * K + k] = h;
        Olo[(size_t)blockIdx.x * K + k] = l;
    }
}

// ---------------- row softmax of S, fp16 splits ----------------
__global__ void __launch_bounds__(256)
softmax_rows(const float* __restrict__ S,
             __half* __restrict__ Phi, __half* __restrict__ Plo, int M)
{
    __shared__ float red[32];
    const float* Sr = S + (size_t)blockIdx.x * M;
    const int nit = M / 256;
    float v[8];
    float mx = -INFINITY;
    for (int i = 0; i < nit; i++) {
        v[i] = Sr[threadIdx.x + i * 256];
        mx = fmaxf(mx, v[i]);
    }
    mx = blockReduceMax(mx, red);
    float s = 0.f;
    for (int i = 0; i < nit; i++) { v[i] = expf(v[i] - mx); s += v[i]; }
    s = blockReduceSum(s, red);
    float inv = 1.f / s;
    for (int i = 0; i < nit; i++) {
        float p = v[i] * inv;
        __half h, l; split2h(p, h, l);
        size_t o = (size_t)blockIdx.x * M + threadIdx.x + i * 256;
        Phi[o] = h; Plo[o] = l;
    }
}

// ---------------- launch ----------------
extern "C" void kernel_launch(void* const* d_in, const int* in_sizes, int n_in,
                              void* d_out, int out_size)
{
    const float* H_rna  = (const float*)d_in[0];
    const float* H_drug = (const float*)d_in[1];
    const float* U      = (const float*)d_in[2];
    const float* V      = (const float*)d_in[3];
    const float* q      = (const float*)d_in[4];
    const float* g_rna  = (const float*)d_in[5];
    const float* b_rna  = (const float*)d_in[6];
    const float* g_drug = (const float*)d_in[7];
    const float* b_drug = (const float*)d_in[8];

    const int K = in_sizes[4];             // 512
    const int d = in_sizes[2] / K;         // 256
    const int N = in_sizes[0] / d;         // 65536
    const int M = in_sizes[1] / d;         // 2048

    float *pA, *pS, *pT;
    __half *pAhi, *pAlo, *pPhi, *pPlo, *pHrhi, *pHrlo, *pHdhi, *pHdlo, *pVhi, *pVlo;
    __half *pDpThi, *pDpTlo, *pHdThi, *pHdTlo, *pUthi, *pUtlo;
    cudaGetSymbolAddress((void**)&pA,     g_A);
    cudaGetSymbolAddress((void**)&pS,     g_S);
    cudaGetSymbolAddress((void**)&pT,     g_T);
    cudaGetSymbolAddress((void**)&pAhi,   g_Ahi);
    cudaGetSymbolAddress((void**)&pAlo,   g_Alo);
    cudaGetSymbolAddress((void**)&pPhi,   g_Phi);
    cudaGetSymbolAddress((void**)&pPlo,   g_Plo);
    cudaGetSymbolAddress((void**)&pHrhi,  g_Hrhi);
    cudaGetSymbolAddress((void**)&pHrlo,  g_Hrlo);
    cudaGetSymbolAddress((void**)&pHdhi,  g_Hdhi);
    cudaGetSymbolAddress((void**)&pHdlo,  g_Hdlo);
    cudaGetSymbolAddress((void**)&pVhi,   g_Vhi);
    cudaGetSymbolAddress((void**)&pVlo,   g_Vlo);
    cudaGetSymbolAddress((void**)&pDpThi, g_DpThi);
    cudaGetSymbolAddress((void**)&pDpTlo, g_DpTlo);
    cudaGetSymbolAddress((void**)&pHdThi, g_HdThi);
    cudaGetSymbolAddress((void**)&pHdTlo, g_HdTlo);
    cudaGetSymbolAddress((void**)&pUthi,  g_Uthi);
    cudaGetSymbolAddress((void**)&pUtlo,  g_Utlo);

    const int SMEMSZ = 98304;   // 3 stages x 32KB
    cudaFuncSetAttribute(gemm_hmma<0>, cudaFuncAttributeMaxDynamicSharedMemorySize, SMEMSZ);
    cudaFuncSetAttribute(gemm_hmma<1>, cudaFuncAttributeMaxDynamicSharedMemorySize, SMEMSZ);

    // prep: splits / transposes
    split_kernel<<<4096, 256>>>(H_rna, pHrhi, pHrlo, (size_t)N * d);
    split_kernel<<<512, 256>>>(H_drug, pHdhi, pHdlo, (size_t)M * d);
    split_kernel<<<512, 256>>>(V, pVhi, pVlo, (size_t)K * d);
    tsplit_kernel<<<(d * K + 255) / 256, 256>>>(U, pUthi, pUtlo, d, K);        // U[d,K] -> Ut[K,d]
    tsplit_kernel<<<(M * d + 255) / 256, 256>>>(H_drug, pHdThi, pHdTlo, M, d); // Hd[M,d] -> HdT[d,M]

    // 1) T = tanh(Hd @ V^T) -> fp32 [M, K]   (drug branch via HMMA)
    gemm_hmma<1><<<dim3(K / 128, M / 128), 256, SMEMSZ>>>(pHdhi, pHdlo, pVhi, pVlo, pT, d, K);

    // 1b) DpT = LN_rows(T) -> fp16 splits [M, K]
    ln_rows<false><<<M, 128>>>(pT, g_drug, b_drug, nullptr, pDpThi, pDpTlo, K);

    // 2) A = tanh(H_rna @ U) -> fp32 [N, K]
    gemm_hmma<1><<<dim3(K / 128, N / 128), 256, SMEMSZ>>>(pHrhi, pHrlo, pUthi, pUtlo, pA, d, K);

    // 3) LN rows + *q -> fp16 splits
    ln_rows<true><<<N, 128>>>(pA, g_rna, b_rna, q, pAhi, pAlo, K);

    // 4) S = A @ Dp -> fp32 [N, M]
    gemm_hmma<0><<<dim3(M / 128, N / 128), 256, SMEMSZ>>>(pAhi, pAlo, pDpThi, pDpTlo, pS, K, M);

    // 5) P = softmax rows -> fp16 splits
    softmax_rows<<<N, 256>>>(pS, pPhi, pPlo, M);

    // 6) out = P @ H_drug -> fp32 [N, d]
    gemm_hmma<0><<<dim3(d / 128, N / 128), 256, SMEMSZ>>>(pPhi, pPlo, pHdThi, pHdTlo, (float*)d_out, M, d);
}

// round 11
// speedup vs baseline: 2.4952x; 1.0007x over previous
#include <cuda_runtime.h>
#include <cuda_fp16.h>
#include <cstdint>
#include <math.h>

// Fixed shapes (registry): N=65536, M=2048, d=256, K=512
#define NN 65536
#define MM 2048
#define DD 256
#define KK 512
#define LN_EPS 1e-5f

// ---------------- static scratch (no allocations allowed) ----------------
__device__ __align__(256) float  g_A   [(size_t)NN * KK];  // 128MB tanh(H@U) fp32
__device__ __align__(256) float  g_S   [(size_t)NN * MM];  // 512MB scores fp32
__device__ __align__(256) float  g_T   [(size_t)MM * KK];  //   4MB tanh(Hd@V^T) fp32
__device__ __align__(256) __half g_Ahi [(size_t)NN * KK];
__device__ __align__(256) __half g_Alo [(size_t)NN * KK];
__device__ __align__(256) __half g_Hrhi[(size_t)NN * DD];
__device__ __align__(256) __half g_Hrlo[(size_t)NN * DD];
__device__ __align__(256) __half g_Hdhi[(size_t)MM * DD];
__device__ __align__(256) __half g_Hdlo[(size_t)MM * DD];
__device__ __align__(256) __half g_Vhi [(size_t)KK * DD];
__device__ __align__(256) __half g_Vlo [(size_t)KK * DD];
__device__ __align__(256) __half g_DpThi[(size_t)MM * KK];
__device__ __align__(256) __half g_DpTlo[(size_t)MM * KK];
__device__ __align__(256) __half g_HdThi[(size_t)DD * MM];
__device__ __align__(256) __half g_Uthi [(size_t)KK * DD];
__device__ __align__(256) __half g_Utlo [(size_t)KK * DD];

// ---------------- helpers ----------------
__device__ __forceinline__ uint32_t smem_u32(const void* p) {
    uint32_t a;
    asm("{ .reg .u64 t; cvta.to.shared.u64 t, %1; cvt.u32.u64 %0, t; }" : "=r"(a) : "l"(p));
    return a;
}
__device__ __forceinline__ void cp16(uint32_t dst, const void* src) {
    asm volatile("cp.async.cg.shared.global [%0], [%1], 16;" :: "r"(dst), "l"(src));
}
#define CP_COMMIT()  asm volatile("cp.async.commit_group;" ::: "memory")
#define CP_WAIT0()   asm volatile("cp.async.wait_group 0;"  ::: "memory")
#define CP_WAIT1()   asm volatile("cp.async.wait_group 1;"  ::: "memory")

#define LDSM4(r, addr) \
    asm volatile("ldmatrix.sync.aligned.m8n8.x4.shared.b16 {%0,%1,%2,%3}, [%4];" \
        : "=r"((r)[0]), "=r"((r)[1]), "=r"((r)[2]), "=r"((r)[3]) : "r"(addr))

#define MMA16816(c, a, b0, b1) \
    asm volatile("mma.sync.aligned.m16n8k16.row.col.f32.f16.f16.f32 " \
        "{%0,%1,%2,%3}, {%4,%5,%6,%7}, {%8,%9}, {%0,%1,%2,%3};" \
        : "+f"((c)[0]), "+f"((c)[1]), "+f"((c)[2]), "+f"((c)[3]) \
        : "r"((a)[0]), "r"((a)[1]), "r"((a)[2]), "r"((a)[3]), "r"(b0), "r"(b1))

__device__ __forceinline__ void split2h(float x, __half& h, __half& l) {
    h = __float2half(x);
    l = __float2half(x - __half2float(h));
}
__device__ __forceinline__ uint32_t pack2h(float a, float b) {
    __half2 h = __floats2half2_rn(a, b);
    return *(uint32_t*)&h;
}

// ---------------- block reduce helpers ----------------
__device__ __forceinline__ float blockReduceSum(float v, volatile float* sm) {
    int lane = threadIdx.x & 31, w = threadIdx.x >> 5;
    #pragma unroll
    for (int o = 16; o; o >>= 1) v += __shfl_xor_sync(0xffffffffu, v, o);
    __syncthreads();
    if (lane == 0) sm[w] = v;
    __syncthreads();
    if (w == 0) {
        float x = (lane < (int)(blockDim.x >> 5)) ? sm[lane] : 0.f;
        #pragma unroll
        for (int o = 16; o; o >>= 1) x += __shfl_xor_sync(0xffffffffu, x, o);
        if (lane == 0) sm[0] = x;
    }
    __syncthreads();
    float r = sm[0];
    __syncthreads();
    return r;
}

// ============ HMMA GEMM: C[rows,Ncols] = A[rows,Ktot] @ B[Ncols,Ktot]^T ============
// (unchanged from R7: 128x128 tile, BK=32, 3-stage ring, 2 CTA/SM, fp16 x3 split)
template<int EPI>
__global__ void __launch_bounds__(256, 2)
gemm_hmma(const __half* __restrict__ Ahi, const __half* __restrict__ Alo,
          const __half* __restrict__ Bhi, const __half* __restrict__ Blo,
          float* __restrict__ C, int Ktot, int Ncols)
{
    extern __shared__ char smem[];
    const int tid  = threadIdx.x;
    const int wid  = tid >> 5, lane = tid & 31;
    const int row0 = blockIdx.y * 128;
    const int col0 = blockIdx.x * 128;
    const int nch  = Ktot >> 5;

    const uint32_t sb = smem_u32(smem);

    const int wr = wid >> 1;
    const int wc = wid & 1;
    const int lm = lane >> 3;
    const int lr = lane & 7;

    float acc[2][8][4];
    #pragma unroll
    for (int i = 0; i < 2; i++)
        #pragma unroll
        for (int j = 0; j < 8; j++)
            #pragma unroll
            for (int k = 0; k < 4; k++) acc[i][j][k] = 0.f;

    auto load_chunk = [&](int ch, int stage) {
        const int kc0 = ch << 5;
        const uint32_t Ab = sb + (uint32_t)stage * 32768u;
        const uint32_t Bb = Ab + 16384u;
        #pragma unroll
        for (int g = tid; g < 2048; g += 256) {
            int mat = g >> 10;
            int r   = (g >> 3) & 127;
            int s   = g & 7;
            int split = s >> 2;
            int seg   = s & 3;
            const __half* srcb;
            int grow;
            if (mat == 0) { srcb = split ? Alo : Ahi; grow = row0 + r; }
            else          { srcb = split ? Blo : Bhi; grow = col0 + r; }
            const __half* src = srcb + (size_t)grow * Ktot + kc0 + seg * 8;
            uint32_t off = (uint32_t)(r * 128 + split * 64 + seg * 16);
            uint32_t dst = (mat ? Bb : Ab) + (off ^ ((off >> 3) & 0x70));
            cp16(dst, src);
        }
        CP_COMMIT();
    };

    auto compute = [&](int stage) {
        const uint32_t Ab = sb + (uint32_t)stage * 32768u;
        const uint32_t Bb = Ab + 16384u;
        #pragma unroll
        for (int ks = 0; ks < 2; ks++) {
            uint32_t ah[2][4], al[2][4];
            #pragma unroll
            for (int mt = 0; mt < 2; mt++) {
                int r = wr * 32 + mt * 16 + (lm & 1) * 8 + lr;
                int ch = ks * 32 + (lm >> 1) * 16;
                uint32_t rowa = Ab + (uint32_t)(r * 128);
                LDSM4(ah[mt], rowa + (uint32_t)( ch       ^ ((r & 7) << 4)));
                LDSM4(al[mt], rowa + (uint32_t)((ch + 64) ^ ((r & 7) << 4)));
            }
            uint32_t b[4][4];
            #pragma unroll
            for (int nt2 = 0; nt2 < 4; nt2++) {
                int r = wc * 64 + nt2 * 16 + (lm >> 1) * 8 + lr;
                int cb = ks * 32 + (lm & 1) * 16;
                LDSM4(b[nt2], Bb + (uint32_t)(r * 128) + (uint32_t)(cb ^ ((r & 7) << 4)));
            }
            #pragma unroll
            for (int mt = 0; mt < 2; mt++)
                #pragma unroll
                for (int nt = 0; nt < 8; nt++)
                    MMA16816(acc[mt][nt], ah[mt],
                             b[nt >> 1][(nt & 1) * 2], b[nt >> 1][(nt & 1) * 2 + 1]);
            #pragma unroll
            for (int mt = 0; mt < 2; mt++)
                #pragma unroll
                for (int nt = 0; nt < 8; nt++)
                    MMA16816(acc[mt][nt], al[mt],
                             b[nt >> 1][(nt & 1) * 2], b[nt >> 1][(nt & 1) * 2 + 1]);
            #pragma unroll
            for (int nt2 = 0; nt2 < 4; nt2++) {
                int r = wc * 64 + nt2 * 16 + (lm >> 1) * 8 + lr;
                int cb = 64 + ks * 32 + (lm & 1) * 16;
                LDSM4(b[nt2], Bb + (uint32_t)(r * 128) + (uint32_t)(cb ^ ((r & 7) << 4)));
            }
            #pragma unroll
            for (int mt = 0; mt < 2; mt++)
                #pragma unroll
                for (int nt = 0; nt < 8; nt++)
                    MMA16816(acc[mt][nt], ah[mt],
                             b[nt >> 1][(nt & 1) * 2], b[nt >> 1][(nt & 1) * 2 + 1]);
        }
    };

    load_chunk(0, 0);
    load_chunk(1, 1);
    for (int i = 0; i < nch; i++) {
        if (i + 1 < nch) CP_WAIT1(); else CP_WAIT0();
        __syncthreads();
        if (i + 2 < nch) {
            int st = i + 2; st -= (st / 3) * 3;
            load_chunk(i + 2, st);
        }
        int cs = i; cs -= (cs / 3) * 3;
        compute(cs);
    }

    #pragma unroll
    for (int mt = 0; mt < 2; mt++) {
        #pragma unroll
        for (int nt = 0; nt < 8; nt++) {
            int r = row0 + wr * 32 + mt * 16 + (lane >> 2);
            int c = col0 + wc * 64 + nt * 8 + (lane & 3) * 2;
            float2 v0 = make_float2(acc[mt][nt][0], acc[mt][nt][1]);
            float2 v1 = make_float2(acc[mt][nt][2], acc[mt][nt][3]);
            if (EPI == 1) {
                v0.x = tanhf(v0.x); v0.y = tanhf(v0.y);
                v1.x = tanhf(v1.x); v1.y = tanhf(v1.y);
            }
            *(float2*)&C[(size_t)r * Ncols + c]       = v0;
            *(float2*)&C[(size_t)(r + 8) * Ncols + c] = v1;
        }
    }
}

// ============ fused softmax + O = softmax(S) @ Hd ============
// Grid: N/128.  Block: 512 threads (16 warps: wr 0..7 x 16 rows, wc 0..1 x 128 d-cols).
// Phase 1: row max over S (exp-free). Phase 2: stream HdT-hi tiles (B), build
// P = exp(S - max) fragments in registers as hi/lo fp32 split, 2-product MMA
// (PhBh + PlBh), accumulate row sums on the fly, scale by 1/l in epilogue.
__global__ void __launch_bounds__(512, 1)
softmax_pv(const float* __restrict__ S, const __half* __restrict__ HdThi,
           float* __restrict__ O, int M, int d)
{
    extern __shared__ char smem[];
    float* smax = (float*)(smem + 65536);
    float* ssum = smax + 128;
    float* pred = ssum + 128;       // 512 partial maxima
    const uint32_t sb = smem_u32(smem);
    const int tid  = threadIdx.x;
    const int wid  = tid >> 5, lane = tid & 31;
    const int wr   = wid >> 1, wc = wid & 1;
    const int lm   = lane >> 3, lr = lane & 7;
    const int row0 = blockIdx.x * 128;

    // ---- phase 1: row max (4 threads per row) ----
    {
        int row  = row0 + (tid >> 2);
        int part = tid & 3;
        const float4* p = (const float4*)(S + (size_t)row * M + part * (M >> 2));
        float m = -INFINITY;
        for (int i = 0; i < (M >> 4); i++) {
            float4 v = p[i];
            m = fmaxf(m, fmaxf(fmaxf(v.x, v.y), fmaxf(v.z, v.w)));
        }
        pred[tid] = m;
    }
    __syncthreads();
    if (tid < 128) {
        smax[tid] = fmaxf(fmaxf(pred[tid*4], pred[tid*4+1]),
                          fmaxf(pred[tid*4+2], pred[tid*4+3]));
        ssum[tid] = 0.f;
    }
    __syncthreads();

    // ---- phase 2 ----
    const int nch  = M >> 5;                   // m-chunks of 32
    const int r0l  = wr * 16 + (lane >> 2);    // this thread's local rows: r0l, r0l+8
    const float mx0 = smax[r0l];
    const float mx1 = smax[r0l + 8];
    const float* Sr0 = S + (size_t)(row0 + r0l) * M + (lane & 3) * 2;
    const float* Sr1 = S + (size_t)(row0 + r0l + 8) * M + (lane & 3) * 2;

    float acc[16][4];
    #pragma unroll
    for (int i = 0; i < 16; i++)
        #pragma unroll
        for (int j = 0; j < 4; j++) acc[i][j] = 0.f;
    float psum0 = 0.f, psum1 = 0.f;

    auto loadB = [&](int ch, int buf) {
        const int m0 = ch << 5;
        const uint32_t Bb = sb + (uint32_t)buf * 32768u;
        #pragma unroll
        for (int g = tid; g < 1024; g += 512) {     // 256 d-rows x 4 x 16B (hi only)
            int r = g >> 2, seg = g & 3;
            const __half* src = HdThi + (size_t)r * M + m0 + seg * 8;
            uint32_t off = (uint32_t)(r * 128 + seg * 16);
            cp16(Bb + (off ^ ((off >> 3) & 0x70)), src);
        }
        CP_COMMIT();
    };
    auto loadS = [&](int ch, float2* sp) {
        const int c0 = ch << 5;
        sp[0] = *(const float2*)(Sr0 + c0);
        sp[1] = *(const float2*)(Sr0 + c0 + 8);
        sp[2] = *(const float2*)(Sr0 + c0 + 16);
        sp[3] = *(const float2*)(Sr0 + c0 + 24);
        sp[4] = *(const float2*)(Sr1 + c0);
        sp[5] = *(const float2*)(Sr1 + c0 + 8);
        sp[6] = *(const float2*)(Sr1 + c0 + 16);
        sp[7] = *(const float2*)(Sr1 + c0 + 24);
    };

    float2 spc[8];
    loadB(0, 0);
    loadS(0, spc);

    for (int c = 0; c < nch; c++) {
        float2 spn[8];
        if (c + 1 < nch) {
            loadB(c + 1, (c + 1) & 1);
            loadS(c + 1, spn);
            CP_WAIT1();
        } else {
            CP_WAIT0();
        }
        __syncthreads();

        const uint32_t Bb = sb + (uint32_t)(c & 1) * 32768u;
        #pragma unroll
        for (int ks = 0; ks < 2; ks++) {
            // P fragment: rows r0l (sp[2ks],sp[2ks+1]) and r0l+8 (sp[4+2ks],...)
            float e00 = __expf(spc[2*ks    ].x - mx0), e01 = __expf(spc[2*ks    ].y - mx0);
            float e02 = __expf(spc[2*ks + 1].x - mx0), e03 = __expf(spc[2*ks + 1].y - mx0);
            float e10 = __expf(spc[4 + 2*ks    ].x - mx1), e11 = __expf(spc[4 + 2*ks    ].y - mx1);
            float e12 = __expf(spc[4 + 2*ks + 1].x - mx1), e13 = __expf(spc[4 + 2*ks + 1].y - mx1);
            psum0 += e00 + e01 + e02 + e03;
            psum1 += e10 + e11 + e12 + e13;
            uint32_t ah[4], al[4];
            ah[0] = pack2h(e00, e01); ah[1] = pack2h(e10, e11);
            ah[2] = pack2h(e02, e03); ah[3] = pack2h(e12, e13);
            {   // residuals
                __half2 h;
                h = *(__half2*)&ah[0]; al[0] = pack2h(e00 - __low2float(h), e01 - __high2float(h));
                h = *(__half2*)&ah[1]; al[1] = pack2h(e10 - __low2float(h), e11 - __high2float(h));
                h = *(__half2*)&ah[2]; al[2] = pack2h(e02 - __low2float(h), e03 - __high2float(h));
                h = *(__half2*)&ah[3]; al[3] = pack2h(e12 - __low2float(h), e13 - __high2float(h));
            }
            #pragma unroll
            for (int nt2 = 0; nt2 < 8; nt2++) {
                int r  = wc * 128 + nt2 * 16 + (lm >> 1) * 8 + lr;
                int cb = ks * 32 + (lm & 1) * 16;
                uint32_t b[4];
                LDSM4(b, Bb + (uint32_t)(r * 128) + (uint32_t)(cb ^ ((r & 7) << 4)));
                MMA16816(acc[nt2 * 2    ], ah, b[0], b[1]);
                MMA16816(acc[nt2 * 2    ], al, b[0], b[1]);
                MMA16816(acc[nt2 * 2 + 1], ah, b[2], b[3]);
                MMA16816(acc[nt2 * 2 + 1], al, b[2], b[3]);
            }
        }
        #pragma unroll
        for (int i = 0; i < 8; i++) spc[i] = spn[i];
        __syncthreads();
    }

    // row-sum reduction: quad lanes hold disjoint column sets; wc warps duplicate.
    psum0 += __shfl_xor_sync(0xffffffffu, psum0, 1);
    psum0 += __shfl_xor_sync(0xffffffffu, psum0, 2);
    psum1 += __shfl_xor_sync(0xffffffffu, psum1, 1);
    psum1 += __shfl_xor_sync(0xffffffffu, psum1, 2);
    if ((lane & 3) == 0 && wc == 0) {
        atomicAdd(&ssum[r0l],     psum0);
        atomicAdd(&ssum[r0l + 8], psum1);
    }
    __syncthreads();
    const float inv0 = 1.f / ssum[r0l];
    const float inv1 = 1.f / ssum[r0l + 8];

    #pragma unroll
    for (int nt2 = 0; nt2 < 8; nt2++) {
        #pragma unroll
        for (int j = 0; j < 2; j++) {
            int col = wc * 128 + nt2 * 16 + j * 8 + (lane & 3) * 2;
            float* a4 = acc[nt2 * 2 + j];
            *(float2*)&O[(size_t)(row0 + r0l)     * d + col] =
                make_float2(a4[0] * inv0, a4[1] * inv0);
            *(float2*)&O[(size_t)(row0 + r0l + 8) * d + col] =
                make_float2(a4[2] * inv1, a4[3] * inv1);
        }
    }
}

// ---------------- prep kernels ----------------
__global__ void split_kernel(const float* __restrict__ in,
                             __half* __restrict__ hi, __half* __restrict__ lo, size_t n)
{
    for (size_t i = (size_t)blockIdx.x * blockDim.x + threadIdx.x; i < n;
         i += (size_t)gridDim.x * blockDim.x) {
        __half h, l; split2h(in[i], h, l);
        hi[i] = h; lo[i] = l;
    }
}

__global__ void tsplit_kernel(const float* __restrict__ in,
                              __half* __restrict__ hiT, __half* __restrict__ loT,
                              int R, int C)
{
    int idx = blockIdx.x * blockDim.x + threadIdx.x;
    if (idx < R * C) {
        int r = idx / C, c = idx % C;
        __half h, l; split2h(in[idx], h, l);
        hiT[(size_t)c * R + r] = h;
        if (loT) loT[(size_t)c * R + r] = l;
    }
}

// ---------------- row LayerNorm (+ optional *q), fp16 split outputs ----------------
template<bool QMUL>
__global__ void __launch_bounds__(128)
ln_rows(const float* __restrict__ A, const float* __restrict__ g,
        const float* __restrict__ b, const float* __restrict__ q,
        __half* __restrict__ Ohi, __half* __restrict__ Olo, int K)
{
    __shared__ float red[32];
    const float* Ar = A + (size_t)blockIdx.x * K;
    float s = 0.f, s2 = 0.f;
    for (int k = threadIdx.x * 4; k < K; k += blockDim.x * 4) {
        float4 v = *(const float4*)(Ar + k);
        s  += v.x + v.y + v.z + v.w;
        s2 += v.x * v.x + v.y * v.y + v.z * v.z + v.w * v.w;
    }
    s  = blockReduceSum(s,  red);
    s2 = blockReduceSum(s2, red);
    float mu = s / (float)K;
    float rstd = rsqrtf(s2 / (float)K - mu * mu + LN_EPS);
    for (int k = threadIdx.x * 4; k < K; k += blockDim.x * 4) {
        float4 v  = *(const float4*)(Ar + k);
        float4 gv = *(const float4*)(g + k);
        float4 bv = *(const float4*)(b + k);
        float y0 = (v.x - mu) * rstd * gv.x + bv.x;
        float y1 = (v.y - mu) * rstd * gv.y + bv.y;
        float y2 = (v.z - mu) * rstd * gv.z + bv.z;
        float y3 = (v.w - mu) * rstd * gv.w + bv.w;
        if (QMUL) {
            float4 qv = *(const float4*)(q + k);
            y0 *= qv.x; y1 *= qv.y; y2 *= qv.z; y3 *= qv.w;
        }
        __half h0, l0, h1, l1, h2, l2, h3, l3;
        split2h(y0, h0, l0); split2h(y1, h1, l1);
        split2h(y2, h2, l2); split2h(y3, h3, l3);
        __half2* ph = (__half2*)(Ohi + (size_t)blockIdx.x * K + k);
        __half2* pl = (__half2*)(Olo + (size_t)blockIdx.x * K + k);
        ph[0] = __halves2half2(h0, h1); ph[1] = __halves2half2(h2, h3);
        pl[0] = __halves2half2(l0, l1); pl[1] = __halves2half2(l2, l3);
    }
}

// ---------------- launch ----------------
extern "C" void kernel_launch(void* const* d_in, const int* in_sizes, int n_in,
                              void* d_out, int out_size)
{
    const float* H_rna  = (const float*)d_in[0];
    const float* H_drug = (const float*)d_in[1];
    const float* U      = (const float*)d_in[2];
    const float* V      = (const float*)d_in[3];
    const float* q      = (const float*)d_in[4];
    const float* g_rna  = (const float*)d_in[5];
    const float* b_rna  = (const float*)d_in[6];
    const float* g_drug = (const float*)d_in[7];
    const float* b_drug = (const float*)d_in[8];

    const int K = in_sizes[4];             // 512
    const int d = in_sizes[2] / K;         // 256
    const int N = in_sizes[0] / d;         // 65536
    const int M = in_sizes[1] / d;         // 2048

    float *pA, *pS, *pT;
    __half *pAhi, *pAlo, *pHrhi, *pHrlo, *pHdhi, *pHdlo, *pVhi, *pVlo;
    __half *pDpThi, *pDpTlo, *pHdThi, *pUthi, *pUtlo;
    cudaGetSymbolAddress((void**)&pA,     g_A);
    cudaGetSymbolAddress((void**)&pS,     g_S);
    cudaGetSymbolAddress((void**)&pT,     g_T);
    cudaGetSymbolAddress((void**)&pAhi,   g_Ahi);
    cudaGetSymbolAddress((void**)&pAlo,   g_Alo);
    cudaGetSymbolAddress((void**)&pHrhi,  g_Hrhi);
    cudaGetSymbolAddress((void**)&pHrlo,  g_Hrlo);
    cudaGetSymbolAddress((void**)&pHdhi,  g_Hdhi);
    cudaGetSymbolAddress((void**)&pHdlo,  g_Hdlo);
    cudaGetSymbolAddress((void**)&pVhi,   g_Vhi);
    cudaGetSymbolAddress((void**)&pVlo,   g_Vlo);
    cudaGetSymbolAddress((void**)&pDpThi, g_DpThi);
    cudaGetSymbolAddress((void**)&pDpTlo, g_DpTlo);
    cudaGetSymbolAddress((void**)&pHdThi, g_HdThi);
    cudaGetSymbolAddress((void**)&pUthi,  g_Uthi);
    cudaGetSymbolAddress((void**)&pUtlo,  g_Utlo);

    const int SMEMSZ = 98304;   // gemm: 3 stages x 32KB
    cudaFuncSetAttribute(gemm_hmma<0>, cudaFuncAttributeMaxDynamicSharedMemorySize, SMEMSZ);
    cudaFuncSetAttribute(gemm_hmma<1>, cudaFuncAttributeMaxDynamicSharedMemorySize, SMEMSZ);
    const int SMEMPV = 65536 + 256 * 4 + 512 * 4;   // B dbl-buf + smax/ssum + pred
    cudaFuncSetAttribute(softmax_pv, cudaFuncAttributeMaxDynamicSharedMemorySize, SMEMPV);

    // prep: splits / transposes
    split_kernel<<<4096, 256>>>(H_rna, pHrhi, pHrlo, (size_t)N * d);
    split_kernel<<<512, 256>>>(H_drug, pHdhi, pHdlo, (size_t)M * d);
    split_kernel<<<512, 256>>>(V, pVhi, pVlo, (size_t)K * d);
    tsplit_kernel<<<(d * K + 255) / 256, 256>>>(U, pUthi, pUtlo, d, K);         // U[d,K] -> Ut[K,d]
    tsplit_kernel<<<(M * d + 255) / 256, 256>>>(H_drug, pHdThi, nullptr, M, d); // Hd[M,d] -> HdT[d,M] (hi only)

    // 1) T = tanh(Hd @ V^T) -> fp32 [M, K]   (drug branch via HMMA)
    gemm_hmma<1><<<dim3(K / 128, M / 128), 256, SMEMSZ>>>(pHdhi, pHdlo, pVhi, pVlo, pT, d, K);

    // 1b) DpT = LN_rows(T) -> fp16 splits [M, K]
    ln_rows<false><<<M, 128>>>(pT, g_drug, b_drug, nullptr, pDpThi, pDpTlo, K);

    // 2) A = tanh(H_rna @ U) -> fp32 [N, K]
    gemm_hmma<1><<<dim3(K / 128, N / 128), 256, SMEMSZ>>>(pHrhi, pHrlo, pUthi, pUtlo, pA, d, K);

    // 3) LN rows + *q -> fp16 splits
    ln_rows<true><<<N, 128>>>(pA, g_rna, b_rna, q, pAhi, pAlo, K);

    // 4) S = A @ Dp -> fp32 [N, M]
    gemm_hmma<0><<<dim3(M / 128, N / 128), 256, SMEMSZ>>>(pAhi, pAlo, pDpThi, pDpTlo, pS, K, M);

    // 5+6) out = softmax(S) @ H_drug  (fused, P never materialized)
    softmax_pv<<<N / 128, 512, SMEMPV>>>(pS, pHdThi, (float*)d_out, M, d);
}

// round 12
// speedup vs baseline: 2.5923x; 1.0389x over previous
#include <cuda_runtime.h>
#include <cuda_fp16.h>
#include <cstdint>
#include <math.h>

// Fixed shapes (registry): N=65536, M=2048, d=256, K=512
#define NN 65536
#define MM 2048
#define DD 256
#define KK 512
#define LN_EPS 1e-5f

// ---------------- static scratch (no allocations allowed) ----------------
__device__ __align__(256) float  g_A   [(size_t)NN * KK];  // 128MB tanh(H@U) fp32
__device__ __align__(256) float  g_S   [(size_t)NN * MM];  // 512MB scores fp32
__device__ __align__(256) float  g_T   [(size_t)MM * KK];  //   4MB tanh(Hd@V^T) fp32
__device__ __align__(256) float  g_rowmax[NN];             // row maxima of S
__device__ __align__(256) __half g_Ahi [(size_t)NN * KK];
__device__ __align__(256) __half g_Alo [(size_t)NN * KK];
__device__ __align__(256) __half g_Hrhi[(size_t)NN * DD];
__device__ __align__(256) __half g_Hrlo[(size_t)NN * DD];
__device__ __align__(256) __half g_Hdhi[(size_t)MM * DD];
__device__ __align__(256) __half g_Hdlo[(size_t)MM * DD];
__device__ __align__(256) __half g_Vhi [(size_t)KK * DD];
__device__ __align__(256) __half g_Vlo [(size_t)KK * DD];
__device__ __align__(256) __half g_DpThi[(size_t)MM * KK];
__device__ __align__(256) __half g_DpTlo[(size_t)MM * KK];
__device__ __align__(256) __half g_HdThi[(size_t)DD * MM];
__device__ __align__(256) __half g_Uthi [(size_t)KK * DD];
__device__ __align__(256) __half g_Utlo [(size_t)KK * DD];

// ---------------- helpers ----------------
__device__ __forceinline__ uint32_t smem_u32(const void* p) {
    uint32_t a;
    asm("{ .reg .u64 t; cvta.to.shared.u64 t, %1; cvt.u32.u64 %0, t; }" : "=r"(a) : "l"(p));
    return a;
}
__device__ __forceinline__ void cp16(uint32_t dst, const void* src) {
    asm volatile("cp.async.cg.shared.global [%0], [%1], 16;" :: "r"(dst), "l"(src));
}
#define CP_COMMIT()  asm volatile("cp.async.commit_group;" ::: "memory")
#define CP_WAIT0()   asm volatile("cp.async.wait_group 0;"  ::: "memory")
#define CP_WAIT1()   asm volatile("cp.async.wait_group 1;"  ::: "memory")

#define LDSM4(r, addr) \
    asm volatile("ldmatrix.sync.aligned.m8n8.x4.shared.b16 {%0,%1,%2,%3}, [%4];" \
        : "=r"((r)[0]), "=r"((r)[1]), "=r"((r)[2]), "=r"((r)[3]) : "r"(addr))

#define MMA16816(c, a, b0, b1) \
    asm volatile("mma.sync.aligned.m16n8k16.row.col.f32.f16.f16.f32 " \
        "{%0,%1,%2,%3}, {%4,%5,%6,%7}, {%8,%9}, {%0,%1,%2,%3};" \
        : "+f"((c)[0]), "+f"((c)[1]), "+f"((c)[2]), "+f"((c)[3]) \
        : "r"((a)[0]), "r"((a)[1]), "r"((a)[2]), "r"((a)[3]), "r"(b0), "r"(b1))

__device__ __forceinline__ void split2h(float x, __half& h, __half& l) {
    h = __float2half(x);
    l = __float2half(x - __half2float(h));
}
__device__ __forceinline__ uint32_t pack2h(float a, float b) {
    __half2 h = __floats2half2_rn(a, b);
    return *(uint32_t*)&h;
}
__device__ __forceinline__ void atomicMaxFloat(float* addr, float val) {
    int* ia = (int*)addr;
    int old = *ia;
    while (__int_as_float(old) < val) {
        int assumed = old;
        old = atomicCAS(ia, assumed, __float_as_int(val));
        if (old == assumed) break;
    }
}

// ---------------- block reduce helpers ----------------
__device__ __forceinline__ float blockReduceSum(float v, volatile float* sm) {
    int lane = threadIdx.x & 31, w = threadIdx.x >> 5;
    #pragma unroll
    for (int o = 16; o; o >>= 1) v += __shfl_xor_sync(0xffffffffu, v, o);
    __syncthreads();
    if (lane == 0) sm[w] = v;
    __syncthreads();
    if (w == 0) {
        float x = (lane < (int)(blockDim.x >> 5)) ? sm[lane] : 0.f;
        #pragma unroll
        for (int o = 16; o; o >>= 1) x += __shfl_xor_sync(0xffffffffu, x, o);
        if (lane == 0) sm[0] = x;
    }
    __syncthreads();
    float r = sm[0];
    __syncthreads();
    return r;
}

// ============ HMMA GEMM: C[rows,Ncols] = A[rows,Ktot] @ B[Ncols,Ktot]^T ============
// 128x128 tile, BK=32, 3-stage ring, 2 CTA/SM, fp16 x3 split.
// EPI: 0 = none, 1 = tanh, 2 = none + fused per-row max -> rowmax[] (for softmax)
template<int EPI>
__global__ void __launch_bounds__(256, 2)
gemm_hmma(const __half* __restrict__ Ahi, const __half* __restrict__ Alo,
          const __half* __restrict__ Bhi, const __half* __restrict__ Blo,
          float* __restrict__ C, int Ktot, int Ncols, float* __restrict__ rowmax)
{
    extern __shared__ char smem[];
    const int tid  = threadIdx.x;
    const int wid  = tid >> 5, lane = tid & 31;
    const int row0 = blockIdx.y * 128;
    const int col0 = blockIdx.x * 128;
    const int nch  = Ktot >> 5;

    const uint32_t sb = smem_u32(smem);

    const int wr = wid >> 1;
    const int wc = wid & 1;
    const int lm = lane >> 3;
    const int lr = lane & 7;

    float acc[2][8][4];
    #pragma unroll
    for (int i = 0; i < 2; i++)
        #pragma unroll
        for (int j = 0; j < 8; j++)
            #pragma unroll
            for (int k = 0; k < 4; k++) acc[i][j][k] = 0.f;

    auto load_chunk = [&](int ch, int stage) {
        const int kc0 = ch << 5;
        const uint32_t Ab = sb + (uint32_t)stage * 32768u;
        const uint32_t Bb = Ab + 16384u;
        #pragma unroll
        for (int g = tid; g < 2048; g += 256) {
            int mat = g >> 10;
            int r   = (g >> 3) & 127;
            int s   = g & 7;
            int split = s >> 2;
            int seg   = s & 3;
            const __half* srcb;
            int grow;
            if (mat == 0) { srcb = split ? Alo : Ahi; grow = row0 + r; }
            else          { srcb = split ? Blo : Bhi; grow = col0 + r; }
            const __half* src = srcb + (size_t)grow * Ktot + kc0 + seg * 8;
            uint32_t off = (uint32_t)(r * 128 + split * 64 + seg * 16);
            uint32_t dst = (mat ? Bb : Ab) + (off ^ ((off >> 3) & 0x70));
            cp16(dst, src);
        }
        CP_COMMIT();
    };

    auto compute = [&](int stage) {
        const uint32_t Ab = sb + (uint32_t)stage * 32768u;
        const uint32_t Bb = Ab + 16384u;
        #pragma unroll
        for (int ks = 0; ks < 2; ks++) {
            uint32_t ah[2][4], al[2][4];
            #pragma unroll
            for (int mt = 0; mt < 2; mt++) {
                int r = wr * 32 + mt * 16 + (lm & 1) * 8 + lr;
                int ch = ks * 32 + (lm >> 1) * 16;
                uint32_t rowa = Ab + (uint32_t)(r * 128);
                LDSM4(ah[mt], rowa + (uint32_t)( ch       ^ ((r & 7) << 4)));
                LDSM4(al[mt], rowa + (uint32_t)((ch + 64) ^ ((r & 7) << 4)));
            }
            uint32_t b[4][4];
            #pragma unroll
            for (int nt2 = 0; nt2 < 4; nt2++) {
                int r = wc * 64 + nt2 * 16 + (lm >> 1) * 8 + lr;
                int cb = ks * 32 + (lm & 1) * 16;
                LDSM4(b[nt2], Bb + (uint32_t)(r * 128) + (uint32_t)(cb ^ ((r & 7) << 4)));
            }
            #pragma unroll
            for (int mt = 0; mt < 2; mt++)
                #pragma unroll
                for (int nt = 0; nt < 8; nt++)
                    MMA16816(acc[mt][nt], ah[mt],
                             b[nt >> 1][(nt & 1) * 2], b[nt >> 1][(nt & 1) * 2 + 1]);
            #pragma unroll
            for (int mt = 0; mt < 2; mt++)
                #pragma unroll
                for (int nt = 0; nt < 8; nt++)
                    MMA16816(acc[mt][nt], al[mt],
                             b[nt >> 1][(nt & 1) * 2], b[nt >> 1][(nt & 1) * 2 + 1]);
            #pragma unroll
            for (int nt2 = 0; nt2 < 4; nt2++) {
                int r = wc * 64 + nt2 * 16 + (lm >> 1) * 8 + lr;
                int cb = 64 + ks * 32 + (lm & 1) * 16;
                LDSM4(b[nt2], Bb + (uint32_t)(r * 128) + (uint32_t)(cb ^ ((r & 7) << 4)));
            }
            #pragma unroll
            for (int mt = 0; mt < 2; mt++)
                #pragma unroll
                for (int nt = 0; nt < 8; nt++)
                    MMA16816(acc[mt][nt], ah[mt],
                             b[nt >> 1][(nt & 1) * 2], b[nt >> 1][(nt & 1) * 2 + 1]);
        }
    };

    load_chunk(0, 0);
    load_chunk(1, 1);
    for (int i = 0; i < nch; i++) {
        if (i + 1 < nch) CP_WAIT1(); else CP_WAIT0();
        __syncthreads();
        if (i + 2 < nch) {
            int st = i + 2; st -= (st / 3) * 3;
            load_chunk(i + 2, st);
        }
        int cs = i; cs -= (cs / 3) * 3;
        compute(cs);
    }

    #pragma unroll
    for (int mt = 0; mt < 2; mt++) {
        float rmax0 = -INFINITY, rmax1 = -INFINITY;   // rows r, r+8 of this mt
        #pragma unroll
        for (int nt = 0; nt < 8; nt++) {
            int r = row0 + wr * 32 + mt * 16 + (lane >> 2);
            int c = col0 + wc * 64 + nt * 8 + (lane & 3) * 2;
            float2 v0 = make_float2(acc[mt][nt][0], acc[mt][nt][1]);
            float2 v1 = make_float2(acc[mt][nt][2], acc[mt][nt][3]);
            if (EPI == 1) {
                v0.x = tanhf(v0.x); v0.y = tanhf(v0.y);
                v1.x = tanhf(v1.x); v1.y = tanhf(v1.y);
            }
            if (EPI == 2) {
                rmax0 = fmaxf(rmax0, fmaxf(v0.x, v0.y));
                rmax1 = fmaxf(rmax1, fmaxf(v1.x, v1.y));
            }
            *(float2*)&C[(size_t)r * Ncols + c]       = v0;
            *(float2*)&C[(size_t)(r + 8) * Ncols + c] = v1;
        }
        if (EPI == 2) {
            // quad reduce (lanes differ only in columns within the quad)
            rmax0 = fmaxf(rmax0, __shfl_xor_sync(0xffffffffu, rmax0, 1));
            rmax0 = fmaxf(rmax0, __shfl_xor_sync(0xffffffffu, rmax0, 2));
            rmax1 = fmaxf(rmax1, __shfl_xor_sync(0xffffffffu, rmax1, 1));
            rmax1 = fmaxf(rmax1, __shfl_xor_sync(0xffffffffu, rmax1, 2));
            if ((lane & 3) == 0) {
                int r = row0 + wr * 32 + mt * 16 + (lane >> 2);
                atomicMaxFloat(&rowmax[r],     rmax0);
                atomicMaxFloat(&rowmax[r + 8], rmax1);
            }
        }
    }
}

// ---------------- rowmax init ----------------
__global__ void rowmax_init(float* __restrict__ rm, int n)
{
    int i = blockIdx.x * blockDim.x + threadIdx.x;
    if (i < n) rm[i] = -INFINITY;
}

// ============ fused softmax + O = softmax(S) @ Hd ============
// Row maxima precomputed by stage-4 epilogue (g_rowmax). Single pass over S:
// P = exp(S - max) built in MMA A-fragment registers as hi/lo fp32 split,
// 2-product MMA (PhBh + PlBh), row sums accumulated on the fly, 1/l in epilogue.
__global__ void __launch_bounds__(512, 1)
softmax_pv(const float* __restrict__ S, const __half* __restrict__ HdThi,
           const float* __restrict__ rowmax, float* __restrict__ O, int M, int d)
{
    extern __shared__ char smem[];
    float* smax = (float*)(smem + 65536);
    float* ssum = smax + 128;
    const uint32_t sb = smem_u32(smem);
    const int tid  = threadIdx.x;
    const int wid  = tid >> 5, lane = tid & 31;
    const int wr   = wid >> 1, wc = wid & 1;
    const int lm   = lane >> 3, lr = lane & 7;
    const int row0 = blockIdx.x * 128;

    if (tid < 128) {
        smax[tid] = rowmax[row0 + tid];
        ssum[tid] = 0.f;
    }
    __syncthreads();

    const int nch  = M >> 5;                   // m-chunks of 32
    const int r0l  = wr * 16 + (lane >> 2);    // this thread's local rows: r0l, r0l+8
    const float mx0 = smax[r0l];
    const float mx1 = smax[r0l + 8];
    const float* Sr0 = S + (size_t)(row0 + r0l) * M + (lane & 3) * 2;
    const float* Sr1 = S + (size_t)(row0 + r0l + 8) * M + (lane & 3) * 2;

    float acc[16][4];
    #pragma unroll
    for (int i = 0; i < 16; i++)
        #pragma unroll
        for (int j = 0; j < 4; j++) acc[i][j] = 0.f;
    float psum0 = 0.f, psum1 = 0.f;

    auto loadB = [&](int ch, int buf) {
        const int m0 = ch << 5;
        const uint32_t Bb = sb + (uint32_t)buf * 32768u;
        #pragma unroll
        for (int g = tid; g < 1024; g += 512) {     // 256 d-rows x 4 x 16B (hi only)
            int r = g >> 2, seg = g & 3;
            const __half* src = HdThi + (size_t)r * M + m0 + seg * 8;
            uint32_t off = (uint32_t)(r * 128 + seg * 16);
            cp16(Bb + (off ^ ((off >> 3) & 0x70)), src);
        }
        CP_COMMIT();
    };
    auto loadS = [&](int ch, float2* sp) {
        const int c0 = ch << 5;
        sp[0] = *(const float2*)(Sr0 + c0);
        sp[1] = *(const float2*)(Sr0 + c0 + 8);
        sp[2] = *(const float2*)(Sr0 + c0 + 16);
        sp[3] = *(const float2*)(Sr0 + c0 + 24);
        sp[4] = *(const float2*)(Sr1 + c0);
        sp[5] = *(const float2*)(Sr1 + c0 + 8);
        sp[6] = *(const float2*)(Sr1 + c0 + 16);
        sp[7] = *(const float2*)(Sr1 + c0 + 24);
    };

    float2 spc[8];
    loadB(0, 0);
    loadS(0, spc);

    for (int c = 0; c < nch; c++) {
        float2 spn[8];
        if (c + 1 < nch) {
            loadB(c + 1, (c + 1) & 1);
            loadS(c + 1, spn);
            CP_WAIT1();
        } else {
            CP_WAIT0();
        }
        __syncthreads();

        const uint32_t Bb = sb + (uint32_t)(c & 1) * 32768u;
        #pragma unroll
        for (int ks = 0; ks < 2; ks++) {
            float e00 = __expf(spc[2*ks    ].x - mx0), e01 = __expf(spc[2*ks    ].y - mx0);
            float e02 = __expf(spc[2*ks + 1].x - mx0), e03 = __expf(spc[2*ks + 1].y - mx0);
            float e10 = __expf(spc[4 + 2*ks    ].x - mx1), e11 = __expf(spc[4 + 2*ks    ].y - mx1);
            float e12 = __expf(spc[4 + 2*ks + 1].x - mx1), e13 = __expf(spc[4 + 2*ks + 1].y - mx1);
            psum0 += e00 + e01 + e02 + e03;
            psum1 += e10 + e11 + e12 + e13;
            uint32_t ah[4], al[4];
            ah[0] = pack2h(e00, e01); ah[1] = pack2h(e10, e11);
            ah[2] = pack2h(e02, e03); ah[3] = pack2h(e12, e13);
            {   // residuals
                __half2 h;
                h = *(__half2*)&ah[0]; al[0] = pack2h(e00 - __low2float(h), e01 - __high2float(h));
                h = *(__half2*)&ah[1]; al[1] = pack2h(e10 - __low2float(h), e11 - __high2float(h));
                h = *(__half2*)&ah[2]; al[2] = pack2h(e02 - __low2float(h), e03 - __high2float(h));
                h = *(__half2*)&ah[3]; al[3] = pack2h(e12 - __low2float(h), e13 - __high2float(h));
            }
            #pragma unroll
            for (int nt2 = 0; nt2 < 8; nt2++) {
                int r  = wc * 128 + nt2 * 16 + (lm >> 1) * 8 + lr;
                int cb = ks * 32 + (lm & 1) * 16;
                uint32_t b[4];
                LDSM4(b, Bb + (uint32_t)(r * 128) + (uint32_t)(cb ^ ((r & 7) << 4)));
                MMA16816(acc[nt2 * 2    ], ah, b[0], b[1]);
                MMA16816(acc[nt2 * 2    ], al, b[0], b[1]);
                MMA16816(acc[nt2 * 2 + 1], ah, b[2], b[3]);
                MMA16816(acc[nt2 * 2 + 1], al, b[2], b[3]);
            }
        }
        #pragma unroll
        for (int i = 0; i < 8; i++) spc[i] = spn[i];
        __syncthreads();
    }

    // row-sum reduction: quad lanes hold disjoint column sets; wc warps duplicate.
    psum0 += __shfl_xor_sync(0xffffffffu, psum0, 1);
    psum0 += __shfl_xor_sync(0xffffffffu, psum0, 2);
    psum1 += __shfl_xor_sync(0xffffffffu, psum1, 1);
    psum1 += __shfl_xor_sync(0xffffffffu, psum1, 2);
    if ((lane & 3) == 0 && wc == 0) {
        atomicAdd(&ssum[r0l],     psum0);
        atomicAdd(&ssum[r0l + 8], psum1);
    }
    __syncthreads();
    const float inv0 = 1.f / ssum[r0l];
    const float inv1 = 1.f / ssum[r0l + 8];

    #pragma unroll
    for (int nt2 = 0; nt2 < 8; nt2++) {
        #pragma unroll
        for (int j = 0; j < 2; j++) {
            int col = wc * 128 + nt2 * 16 + j * 8 + (lane & 3) * 2;
            float* a4 = acc[nt2 * 2 + j];
            *(float2*)&O[(size_t)(row0 + r0l)     * d + col] =
                make_float2(a4[0] * inv0, a4[1] * inv0);
            *(float2*)&O[(size_t)(row0 + r0l + 8) * d + col] =
                make_float2(a4[2] * inv1, a4[3] * inv1);
        }
    }
}

// ---------------- prep kernels ----------------
__global__ void split_kernel(const float* __restrict__ in,
                             __half* __restrict__ hi, __half* __restrict__ lo, size_t n)
{
    for (size_t i = (size_t)blockIdx.x * blockDim.x + threadIdx.x; i < n;
         i += (size_t)gridDim.x * blockDim.x) {
        __half h, l; split2h(in[i], h, l);
        hi[i] = h; lo[i] = l;
    }
}

__global__ void tsplit_kernel(const float* __restrict__ in,
                              __half* __restrict__ hiT, __half* __restrict__ loT,
                              int R, int C)
{
    int idx = blockIdx.x * blockDim.x + threadIdx.x;
    if (idx < R * C) {
        int r = idx / C, c = idx % C;
        __half h, l; split2h(in[idx], h, l);
        hiT[(size_t)c * R + r] = h;
        if (loT) loT[(size_t)c * R + r] = l;
    }
}

// ---------------- row LayerNorm (+ optional *q), fp16 split outputs ----------------
template<bool QMUL>
__global__ void __launch_bounds__(128)
ln_rows(const float* __restrict__ A, const float* __restrict__ g,
        const float* __restrict__ b, const float* __restrict__ q,
        __half* __restrict__ Ohi, __half* __restrict__ Olo, int K)
{
    __shared__ float red[32];
    const float* Ar = A + (size_t)blockIdx.x * K;
    float s = 0.f, s2 = 0.f;
    for (int k = threadIdx.x * 4; k < K; k += blockDim.x * 4) {
        float4 v = *(const float4*)(Ar + k);
        s  += v.x + v.y + v.z + v.w;
        s2 += v.x * v.x + v.y * v.y + v.z * v.z + v.w * v.w;
    }
    s  = blockReduceSum(s,  red);
    s2 = blockReduceSum(s2, red);
    float mu = s / (float)K;
    float rstd = rsqrtf(s2 / (float)K - mu * mu + LN_EPS);
    for (int k = threadIdx.x * 4; k < K; k += blockDim.x * 4) {
        float4 v  = *(const float4*)(Ar + k);
        float4 gv = *(const float4*)(g + k);
        float4 bv = *(const float4*)(b + k);
        float y0 = (v.x - mu) * rstd * gv.x + bv.x;
        float y1 = (v.y - mu) * rstd * gv.y + bv.y;
        float y2 = (v.z - mu) * rstd * gv.z + bv.z;
        float y3 = (v.w - mu) * rstd * gv.w + bv.w;
        if (QMUL) {
            float4 qv = *(const float4*)(q + k);
            y0 *= qv.x; y1 *= qv.y; y2 *= qv.z; y3 *= qv.w;
        }
        __half h0, l0, h1, l1, h2, l2, h3, l3;
        split2h(y0, h0, l0); split2h(y1, h1, l1);
        split2h(y2, h2, l2); split2h(y3, h3, l3);
        __half2* ph = (__half2*)(Ohi + (size_t)blockIdx.x * K + k);
        __half2* pl = (__half2*)(Olo + (size_t)blockIdx.x * K + k);
        ph[0] = __halves2half2(h0, h1); ph[1] = __halves2half2(h2, h3);
        pl[0] = __halves2half2(l0, l1); pl[1] = __halves2half2(l2, l3);
    }
}

// ---------------- launch ----------------
extern "C" void kernel_launch(void* const* d_in, const int* in_sizes, int n_in,
                              void* d_out, int out_size)
{
    const float* H_rna  = (const float*)d_in[0];
    const float* H_drug = (const float*)d_in[1];
    const float* U      = (const float*)d_in[2];
    const float* V      = (const float*)d_in[3];
    const float* q      = (const float*)d_in[4];
    const float* g_rna  = (const float*)d_in[5];
    const float* b_rna  = (const float*)d_in[6];
    const float* g_drug = (const float*)d_in[7];
    const float* b_drug = (const float*)d_in[8];

    const int K = in_sizes[4];             // 512
    const int d = in_sizes[2] / K;         // 256
    const int N = in_sizes[0] / d;         // 65536
    const int M = in_sizes[1] / d;         // 2048

    float *pA, *pS, *pT, *pRM;
    __half *pAhi, *pAlo, *pHrhi, *pHrlo, *pHdhi, *pHdlo, *pVhi, *pVlo;
    __half *pDpThi, *pDpTlo, *pHdThi, *pUthi, *pUtlo;
    cudaGetSymbolAddress((void**)&pA,     g_A);
    cudaGetSymbolAddress((void**)&pS,     g_S);
    cudaGetSymbolAddress((void**)&pT,     g_T);
    cudaGetSymbolAddress((void**)&pRM,    g_rowmax);
    cudaGetSymbolAddress((void**)&pAhi,   g_Ahi);
    cudaGetSymbolAddress((void**)&pAlo,   g_Alo);
    cudaGetSymbolAddress((void**)&pHrhi,  g_Hrhi);
    cudaGetSymbolAddress((void**)&pHrlo,  g_Hrlo);
    cudaGetSymbolAddress((void**)&pHdhi,  g_Hdhi);
    cudaGetSymbolAddress((void**)&pHdlo,  g_Hdlo);
    cudaGetSymbolAddress((void**)&pVhi,   g_Vhi);
    cudaGetSymbolAddress((void**)&pVlo,   g_Vlo);
    cudaGetSymbolAddress((void**)&pDpThi, g_DpThi);
    cudaGetSymbolAddress((void**)&pDpTlo, g_DpTlo);
    cudaGetSymbolAddress((void**)&pHdThi, g_HdThi);
    cudaGetSymbolAddress((void**)&pUthi,  g_Uthi);
    cudaGetSymbolAddress((void**)&pUtlo,  g_Utlo);

    const int SMEMSZ = 98304;   // gemm: 3 stages x 32KB
    cudaFuncSetAttribute(gemm_hmma<0>, cudaFuncAttributeMaxDynamicSharedMemorySize, SMEMSZ);
    cudaFuncSetAttribute(gemm_hmma<1>, cudaFuncAttributeMaxDynamicSharedMemorySize, SMEMSZ);
    cudaFuncSetAttribute(gemm_hmma<2>, cudaFuncAttributeMaxDynamicSharedMemorySize, SMEMSZ);
    const int SMEMPV = 65536 + 256 * 4;   // B dbl-buf + smax/ssum
    cudaFuncSetAttribute(softmax_pv, cudaFuncAttributeMaxDynamicSharedMemorySize, SMEMPV);

    // prep: splits / transposes / rowmax init
    rowmax_init<<<N / 256, 256>>>(pRM, N);
    split_kernel<<<4096, 256>>>(H_rna, pHrhi, pHrlo, (size_t)N * d);
    split_kernel<<<512, 256>>>(H_drug, pHdhi, pHdlo, (size_t)M * d);
    split_kernel<<<512, 256>>>(V, pVhi, pVlo, (size_t)K * d);
    tsplit_kernel<<<(d * K + 255) / 256, 256>>>(U, pUthi, pUtlo, d, K);         // U[d,K] -> Ut[K,d]
    tsplit_kernel<<<(M * d + 255) / 256, 256>>>(H_drug, pHdThi, nullptr, M, d); // Hd[M,d] -> HdT[d,M] (hi only)

    // 1) T = tanh(Hd @ V^T) -> fp32 [M, K]   (drug branch via HMMA)
    gemm_hmma<1><<<dim3(K / 128, M / 128), 256, SMEMSZ>>>(pHdhi, pHdlo, pVhi, pVlo, pT, d, K, nullptr);

    // 1b) DpT = LN_rows(T) -> fp16 splits [M, K]
    ln_rows<false><<<M, 128>>>(pT, g_drug, b_drug, nullptr, pDpThi, pDpTlo, K);

    // 2) A = tanh(H_rna @ U) -> fp32 [N, K]
    gemm_hmma<1><<<dim3(K / 128, N / 128), 256, SMEMSZ>>>(pHrhi, pHrlo, pUthi, pUtlo, pA, d, K, nullptr);

    // 3) LN rows + *q -> fp16 splits
    ln_rows<true><<<N, 128>>>(pA, g_rna, b_rna, q, pAhi, pAlo, K);

    // 4) S = A @ Dp -> fp32 [N, M], fused per-row max into g_rowmax
    gemm_hmma<2><<<dim3(M / 128, N / 128), 256, SMEMSZ>>>(pAhi, pAlo, pDpThi, pDpTlo, pS, K, M, pRM);

    // 5+6) out = softmax(S) @ H_drug  (fused; single pass over S)
    softmax_pv<<<N / 128, 512, SMEMPV>>>(pS, pHdThi, pRM, (float*)d_out, M, d);
}

// round 15
// speedup vs baseline: 2.7966x; 1.0788x over previous
#include <cuda_runtime.h>
#include <cuda_fp16.h>
#include <cstdint>
#include <math.h>

// Fixed shapes (registry): N=65536, M=2048, d=256, K=512
#define NN 65536
#define MM 2048
#define DD 256
#define KK 512
#define LN_EPS 1e-5f

// ---------------- static scratch (no allocations allowed) ----------------
__device__ __align__(256) float  g_S   [(size_t)NN * MM];  // 512MB scores fp32
__device__ __align__(256) float  g_rowmax[NN];             // row maxima of S
__device__ __align__(256) __half g_Ahi [(size_t)NN * KK];
__device__ __align__(256) __half g_Alo [(size_t)NN * KK];
__device__ __align__(256) __half g_Hrhi[(size_t)NN * DD];
__device__ __align__(256) __half g_Hrlo[(size_t)NN * DD];
__device__ __align__(256) __half g_Hdhi[(size_t)MM * DD];
__device__ __align__(256) __half g_Hdlo[(size_t)MM * DD];
__device__ __align__(256) __half g_Vhi [(size_t)KK * DD];
__device__ __align__(256) __half g_Vlo [(size_t)KK * DD];
__device__ __align__(256) __half g_DpThi[(size_t)MM * KK];
__device__ __align__(256) __half g_DpTlo[(size_t)MM * KK];
__device__ __align__(256) __half g_HdThi[(size_t)DD * MM];
__device__ __align__(256) __half g_Uthi [(size_t)KK * DD];
__device__ __align__(256) __half g_Utlo [(size_t)KK * DD];

// ---------------- helpers ----------------
__device__ __forceinline__ uint32_t smem_u32(const void* p) {
    uint32_t a;
    asm("{ .reg .u64 t; cvta.to.shared.u64 t, %1; cvt.u32.u64 %0, t; }" : "=r"(a) : "l"(p));
    return a;
}
__device__ __forceinline__ void cp16(uint32_t dst, const void* src) {
    asm volatile("cp.async.cg.shared.global [%0], [%1], 16;" :: "r"(dst), "l"(src));
}
#define CP_COMMIT()  asm volatile("cp.async.commit_group;" ::: "memory")
#define CP_WAIT0()   asm volatile("cp.async.wait_group 0;"  ::: "memory")
#define CP_WAIT1()   asm volatile("cp.async.wait_group 1;"  ::: "memory")

#define LDSM4(r, addr) \
    asm volatile("ldmatrix.sync.aligned.m8n8.x4.shared.b16 {%0,%1,%2,%3}, [%4];" \
        : "=r"((r)[0]), "=r"((r)[1]), "=r"((r)[2]), "=r"((r)[3]) : "r"(addr))

#define MMA16816(c, a, b0, b1) \
    asm volatile("mma.sync.aligned.m16n8k16.row.col.f32.f16.f16.f32 " \
        "{%0,%1,%2,%3}, {%4,%5,%6,%7}, {%8,%9}, {%0,%1,%2,%3};" \
        : "+f"((c)[0]), "+f"((c)[1]), "+f"((c)[2]), "+f"((c)[3]) \
        : "r"((a)[0]), "r"((a)[1]), "r"((a)[2]), "r"((a)[3]), "r"(b0), "r"(b1))

__device__ __forceinline__ void split2h(float x, __half& h, __half& l) {
    h = __float2half(x);
    l = __float2half(x - __half2float(h));
}
__device__ __forceinline__ uint32_t pack2h(float a, float b) {
    __half2 h = __floats2half2_rn(a, b);
    return *(uint32_t*)&h;
}
__device__ __forceinline__ void atomicMaxFloat(float* addr, float val) {
    int* ia = (int*)addr;
    int old = *ia;
    while (__int_as_float(old) < val) {
        int assumed = old;
        old = atomicCAS(ia, assumed, __float_as_int(val));
        if (old == assumed) break;
    }
}

// ============ HMMA GEMM: C[rows,Ncols] = A[rows,Ktot] @ B[Ncols,Ktot]^T ============
// 128x128 tile, BK=32, 3-stage ring, 2 CTA/SM, fp16 x3 split.
// EPI: 2 = fused per-row max -> rowmax[]
template<int EPI>
__global__ void __launch_bounds__(256, 2)
gemm_hmma(const __half* __restrict__ Ahi, const __half* __restrict__ Alo,
          const __half* __restrict__ Bhi, const __half* __restrict__ Blo,
          float* __restrict__ C, int Ktot, int Ncols, float* __restrict__ rowmax)
{
    extern __shared__ char smem[];
    const int tid  = threadIdx.x;
    const int wid  = tid >> 5, lane = tid & 31;
    const int row0 = blockIdx.y * 128;
    const int col0 = blockIdx.x * 128;
    const int nch  = Ktot >> 5;

    const uint32_t sb = smem_u32(smem);

    const int wr = wid >> 1;
    const int wc = wid & 1;
    const int lm = lane >> 3;
    const int lr = lane & 7;

    float acc[2][8][4];
    #pragma unroll
    for (int i = 0; i < 2; i++)
        #pragma unroll
        for (int j = 0; j < 8; j++)
            #pragma unroll
            for (int k = 0; k < 4; k++) acc[i][j][k] = 0.f;

    auto load_chunk = [&](int ch, int stage) {
        const int kc0 = ch << 5;
        const uint32_t Ab = sb + (uint32_t)stage * 32768u;
        const uint32_t Bb = Ab + 16384u;
        #pragma unroll
        for (int g = tid; g < 2048; g += 256) {
            int mat = g >> 10;
            int r   = (g >> 3) & 127;
            int s   = g & 7;
            int split = s >> 2;
            int seg   = s & 3;
            const __half* srcb;
            int grow;
            if (mat == 0) { srcb = split ? Alo : Ahi; grow = row0 + r; }
            else          { srcb = split ? Blo : Bhi; grow = col0 + r; }
            const __half* src = srcb + (size_t)grow * Ktot + kc0 + seg * 8;
            uint32_t off = (uint32_t)(r * 128 + split * 64 + seg * 16);
            uint32_t dst = (mat ? Bb : Ab) + (off ^ ((off >> 3) & 0x70));
            cp16(dst, src);
        }
        CP_COMMIT();
    };

    auto compute = [&](int stage) {
        const uint32_t Ab = sb + (uint32_t)stage * 32768u;
        const uint32_t Bb = Ab + 16384u;
        #pragma unroll
        for (int ks = 0; ks < 2; ks++) {
            uint32_t ah[2][4], al[2][4];
            #pragma unroll
            for (int mt = 0; mt < 2; mt++) {
                int r = wr * 32 + mt * 16 + (lm & 1) * 8 + lr;
                int ch = ks * 32 + (lm >> 1) * 16;
                uint32_t rowa = Ab + (uint32_t)(r * 128);
                LDSM4(ah[mt], rowa + (uint32_t)( ch       ^ ((r & 7) << 4)));
                LDSM4(al[mt], rowa + (uint32_t)((ch + 64) ^ ((r & 7) << 4)));
            }
            uint32_t b[4][4];
            #pragma unroll
            for (int nt2 = 0; nt2 < 4; nt2++) {
                int r = wc * 64 + nt2 * 16 + (lm >> 1) * 8 + lr;
                int cb = ks * 32 + (lm & 1) * 16;
                LDSM4(b[nt2], Bb + (uint32_t)(r * 128) + (uint32_t)(cb ^ ((r & 7) << 4)));
            }
            #pragma unroll
            for (int mt = 0; mt < 2; mt++)
                #pragma unroll
                for (int nt = 0; nt < 8; nt++)
                    MMA16816(acc[mt][nt], ah[mt],
                             b[nt >> 1][(nt & 1) * 2], b[nt >> 1][(nt & 1) * 2 + 1]);
            #pragma unroll
            for (int mt = 0; mt < 2; mt++)
                #pragma unroll
                for (int nt = 0; nt < 8; nt++)
                    MMA16816(acc[mt][nt], al[mt],
                             b[nt >> 1][(nt & 1) * 2], b[nt >> 1][(nt & 1) * 2 + 1]);
            #pragma unroll
            for (int nt2 = 0; nt2 < 4; nt2++) {
                int r = wc * 64 + nt2 * 16 + (lm >> 1) * 8 + lr;
                int cb = 64 + ks * 32 + (lm & 1) * 16;
                LDSM4(b[nt2], Bb + (uint32_t)(r * 128) + (uint32_t)(cb ^ ((r & 7) << 4)));
            }
            #pragma unroll
            for (int mt = 0; mt < 2; mt++)
                #pragma unroll
                for (int nt = 0; nt < 8; nt++)
                    MMA16816(acc[mt][nt], ah[mt],
                             b[nt >> 1][(nt & 1) * 2], b[nt >> 1][(nt & 1) * 2 + 1]);
        }
    };

    load_chunk(0, 0);
    load_chunk(1, 1);
    for (int i = 0; i < nch; i++) {
        if (i + 1 < nch) CP_WAIT1(); else CP_WAIT0();
        __syncthreads();
        if (i + 2 < nch) {
            int st = i + 2; st -= (st / 3) * 3;
            load_chunk(i + 2, st);
        }
        int cs = i; cs -= (cs / 3) * 3;
        compute(cs);
    }

    #pragma unroll
    for (int mt = 0; mt < 2; mt++) {
        float rmax0 = -INFINITY, rmax1 = -INFINITY;
        #pragma unroll
        for (int nt = 0; nt < 8; nt++) {
            int r = row0 + wr * 32 + mt * 16 + (lane >> 2);
            int c = col0 + wc * 64 + nt * 8 + (lane & 3) * 2;
            float2 v0 = make_float2(acc[mt][nt][0], acc[mt][nt][1]);
            float2 v1 = make_float2(acc[mt][nt][2], acc[mt][nt][3]);
            if (EPI == 2) {
                rmax0 = fmaxf(rmax0, fmaxf(v0.x, v0.y));
                rmax1 = fmaxf(rmax1, fmaxf(v1.x, v1.y));
            }
            *(float2*)&C[(size_t)r * Ncols + c]       = v0;
            *(float2*)&C[(size_t)(r + 8) * Ncols + c] = v1;
        }
        if (EPI == 2) {
            rmax0 = fmaxf(rmax0, __shfl_xor_sync(0xffffffffu, rmax0, 1));
            rmax0 = fmaxf(rmax0, __shfl_xor_sync(0xffffffffu, rmax0, 2));
            rmax1 = fmaxf(rmax1, __shfl_xor_sync(0xffffffffu, rmax1, 1));
            rmax1 = fmaxf(rmax1, __shfl_xor_sync(0xffffffffu, rmax1, 2));
            if ((lane & 3) == 0) {
                int r = row0 + wr * 32 + mt * 16 + (lane >> 2);
                atomicMaxFloat(&rowmax[r],     rmax0);
                atomicMaxFloat(&rowmax[r + 8], rmax1);
            }
        }
    }
}

// ============ fused GEMM + tanh + LayerNorm (+ optional *q) + fp16 split ============
// Tile 64 rows x 512 out-cols (the FULL LN reduction axis), inner dim 256, BK=32 (8 chunks).
// 512 threads: wr = wid>>2 (0..3, 16-row groups), wc = wid&3 (0..3, 128-col groups).
// Two jobs in one grid: blocks [0, nblk1) = job1 (drug), blocks [nblk1, ...) = job2 (rna, QMUL).
__global__ void __launch_bounds__(512, 1)
gemm_ln(const __half* __restrict__ A1hi, const __half* __restrict__ A1lo,
        const __half* __restrict__ B1hi, const __half* __restrict__ B1lo,
        const float* __restrict__ g1, const float* __restrict__ b1,
        __half* __restrict__ O1hi, __half* __restrict__ O1lo, int nblk1,
        const __half* __restrict__ A2hi, const __half* __restrict__ A2lo,
        const __half* __restrict__ B2hi, const __half* __restrict__ B2lo,
        const float* __restrict__ g2, const float* __restrict__ b2,
        const float* __restrict__ q2,
        __half* __restrict__ O2hi, __half* __restrict__ O2lo)
{
    extern __shared__ char smem[];
    float* lnsum  = (float*)(smem + 3 * 73728);
    float* lnsum2 = lnsum + 64;
    const uint32_t sb = smem_u32(smem);

    const bool job2 = (int)blockIdx.x >= nblk1;
    const __half* Ahi = job2 ? A2hi : A1hi;
    const __half* Alo = job2 ? A2lo : A1lo;
    const __half* Bhi = job2 ? B2hi : B1hi;
    const __half* Blo = job2 ? B2lo : B1lo;
    const float*  gp  = job2 ? g2 : g1;
    const float*  bp  = job2 ? b2 : b1;
    __half* Ohi = job2 ? O2hi : O1hi;
    __half* Olo = job2 ? O2lo : O1lo;
    const int row0 = (job2 ? ((int)blockIdx.x - nblk1) : (int)blockIdx.x) * 64;

    const int tid  = threadIdx.x;
    const int wid  = tid >> 5, lane = tid & 31;
    const int wr = wid >> 2, wc = wid & 3;
    const int lm = lane >> 3, lr = lane & 7;

    if (tid < 64) { lnsum[tid] = 0.f; lnsum2[tid] = 0.f; }

    float acc[16][4];
    #pragma unroll
    for (int i = 0; i < 16; i++)
        #pragma unroll
        for (int j = 0; j < 4; j++) acc[i][j] = 0.f;

    auto load_chunk = [&](int ch, int stage) {
        const int kc0 = ch << 5;
        const uint32_t Ab = sb + (uint32_t)stage * 73728u;
        const uint32_t Bb = Ab + 8192u;
        {   // A: 64 rows x 8 segs = 512, one per thread
            int r = tid >> 3, s = tid & 7;
            int split = s >> 2, seg = s & 3;
            const __half* src = (split ? Alo : Ahi) + (size_t)(row0 + r) * 256 + kc0 + seg * 8;
            uint32_t off = (uint32_t)(r * 128 + split * 64 + seg * 16);
            cp16(Ab + (off ^ ((off >> 3) & 0x70)), src);
        }
        #pragma unroll
        for (int g = tid; g < 4096; g += 512) {   // B: 512 rows x 8 segs
            int r = g >> 3, s = g & 7;
            int split = s >> 2, seg = s & 3;
            const __half* src = (split ? Blo : Bhi) + (size_t)r * 256 + kc0 + seg * 8;
            uint32_t off = (uint32_t)(r * 128 + split * 64 + seg * 16);
            cp16(Bb + (off ^ ((off >> 3) & 0x70)), src);
        }
        CP_COMMIT();
    };

    auto compute = [&](int stage) {
        const uint32_t Ab = sb + (uint32_t)stage * 73728u;
        const uint32_t Bb = Ab + 8192u;
        #pragma unroll
        for (int ks = 0; ks < 2; ks++) {
            uint32_t ah[4], al[4];
            {
                int r = wr * 16 + (lm & 1) * 8 + lr;
                int ch = ks * 32 + (lm >> 1) * 16;
                uint32_t rowa = Ab + (uint32_t)(r * 128);
                LDSM4(ah, rowa + (uint32_t)( ch       ^ ((r & 7) << 4)));
                LDSM4(al, rowa + (uint32_t)((ch + 64) ^ ((r & 7) << 4)));
            }
            #pragma unroll
            for (int half = 0; half < 2; half++) {
                uint32_t b[4][4];
                #pragma unroll
                for (int nt2 = 0; nt2 < 4; nt2++) {
                    int gi = half * 4 + nt2;
                    int r  = wc * 128 + gi * 16 + (lm >> 1) * 8 + lr;
                    int cb = ks * 32 + (lm & 1) * 16;
                    LDSM4(b[nt2], Bb + (uint32_t)(r * 128) + (uint32_t)(cb ^ ((r & 7) << 4)));
                }
                #pragma unroll
                for (int nt2 = 0; nt2 < 4; nt2++) {
                    int ai = (half * 4 + nt2) * 2;
                    MMA16816(acc[ai],     ah, b[nt2][0], b[nt2][1]);
                    MMA16816(acc[ai + 1], ah, b[nt2][2], b[nt2][3]);
                    MMA16816(acc[ai],     al, b[nt2][0], b[nt2][1]);
                    MMA16816(acc[ai + 1], al, b[nt2][2], b[nt2][3]);
                }
                #pragma unroll
                for (int nt2 = 0; nt2 < 4; nt2++) {
                    int gi = half * 4 + nt2;
                    int r  = wc * 128 + gi * 16 + (lm >> 1) * 8 + lr;
                    int cb = 64 + ks * 32 + (lm & 1) * 16;
                    LDSM4(b[nt2], Bb + (uint32_t)(r * 128) + (uint32_t)(cb ^ ((r & 7) << 4)));
                }
                #pragma unroll
                for (int nt2 = 0; nt2 < 4; nt2++) {
                    int ai = (half * 4 + nt2) * 2;
                    MMA16816(acc[ai],     ah, b[nt2][0], b[nt2][1]);
                    MMA16816(acc[ai + 1], ah, b[nt2][2], b[nt2][3]);
                }
            }
        }
    };

    load_chunk(0, 0);
    load_chunk(1, 1);
    for (int i = 0; i < 8; i++) {
        if (i + 1 < 8) CP_WAIT1(); else CP_WAIT0();
        __syncthreads();
        if (i + 2 < 8) {
            int st = i + 2; st -= (st / 3) * 3;
            load_chunk(i + 2, st);
        }
        int cs = i; cs -= (cs / 3) * 3;
        compute(cs);
    }

    // ---- epilogue: tanh + per-row LN over 512 cols ----
    const int r0l = wr * 16 + (lane >> 2);   // local rows r0l, r0l+8
    float s0 = 0.f, s20 = 0.f, s1 = 0.f, s21 = 0.f;
    #pragma unroll
    for (int ai = 0; ai < 16; ai++) {
        float v0 = tanhf(acc[ai][0]), v1 = tanhf(acc[ai][1]);
        float v2 = tanhf(acc[ai][2]), v3 = tanhf(acc[ai][3]);
        acc[ai][0] = v0; acc[ai][1] = v1; acc[ai][2] = v2; acc[ai][3] = v3;
        s0 += v0 + v1; s20 += v0 * v0 + v1 * v1;
        s1 += v2 + v3; s21 += v2 * v2 + v3 * v3;
    }
    s0  += __shfl_xor_sync(0xffffffffu, s0, 1);  s0  += __shfl_xor_sync(0xffffffffu, s0, 2);
    s20 += __shfl_xor_sync(0xffffffffu, s20, 1); s20 += __shfl_xor_sync(0xffffffffu, s20, 2);
    s1  += __shfl_xor_sync(0xffffffffu, s1, 1);  s1  += __shfl_xor_sync(0xffffffffu, s1, 2);
    s21 += __shfl_xor_sync(0xffffffffu, s21, 1); s21 += __shfl_xor_sync(0xffffffffu, s21, 2);
    if ((lane & 3) == 0) {
        atomicAdd(&lnsum [r0l],     s0);
        atomicAdd(&lnsum2[r0l],     s20);
        atomicAdd(&lnsum [r0l + 8], s1);
        atomicAdd(&lnsum2[r0l + 8], s21);
    }
    __syncthreads();

    const float mu0   = lnsum[r0l] * (1.f / 512.f);
    const float rstd0 = rsqrtf(lnsum2[r0l] * (1.f / 512.f) - mu0 * mu0 + LN_EPS);
    const float mu1   = lnsum[r0l + 8] * (1.f / 512.f);
    const float rstd1 = rsqrtf(lnsum2[r0l + 8] * (1.f / 512.f) - mu1 * mu1 + LN_EPS);
    const int grow = row0 + r0l;

    #pragma unroll
    for (int ai = 0; ai < 16; ai++) {
        int c = wc * 128 + (ai >> 1) * 16 + (ai & 1) * 8 + (lane & 3) * 2;
        float2 gv = *(const float2*)(gp + c);
        float2 bv = *(const float2*)(bp + c);
        float y0 = (acc[ai][0] - mu0) * rstd0 * gv.x + bv.x;
        float y1 = (acc[ai][1] - mu0) * rstd0 * gv.y + bv.y;
        float y2 = (acc[ai][2] - mu1) * rstd1 * gv.x + bv.x;
        float y3 = (acc[ai][3] - mu1) * rstd1 * gv.y + bv.y;
        if (job2) {
            float2 qv = *(const float2*)(q2 + c);
            y0 *= qv.x; y1 *= qv.y; y2 *= qv.x; y3 *= qv.y;
        }
        __half h0, l0, h1, l1, h2, l2, h3, l3;
        split2h(y0, h0, l0); split2h(y1, h1, l1);
        split2h(y2, h2, l2); split2h(y3, h3, l3);
        *(__half2*)&Ohi[(size_t)grow * 512 + c]       = __halves2half2(h0, h1);
        *(__half2*)&Olo[(size_t)grow * 512 + c]       = __halves2half2(l0, l1);
        *(__half2*)&Ohi[(size_t)(grow + 8) * 512 + c] = __halves2half2(h2, h3);
        *(__half2*)&Olo[(size_t)(grow + 8) * 512 + c] = __halves2half2(l2, l3);
    }
}

// ============ fused softmax + O = softmax(S) @ Hd ============
// B-tile layout: 128B rows with SW128 swizzle, identical formula on store and load
// (proven in R12). Only first 64B of each row used (hi-only Hd). P as fp16-hi single product.
__global__ void __launch_bounds__(512, 1)
softmax_pv(const float* __restrict__ S, const __half* __restrict__ HdThi,
           const float* __restrict__ rowmax, float* __restrict__ O, int M, int d)
{
    extern __shared__ char smem[];
    float* smax = (float*)(smem + 65536);
    float* ssum = smax + 128;
    const uint32_t sb = smem_u32(smem);
    const int tid  = threadIdx.x;
    const int wid  = tid >> 5, lane = tid & 31;
    const int wr   = wid >> 1, wc = wid & 1;
    const int lm   = lane >> 3, lr = lane & 7;
    const int row0 = blockIdx.x * 128;

    if (tid < 128) {
        smax[tid] = rowmax[row0 + tid];
        ssum[tid] = 0.f;
    }
    __syncthreads();

    const int nch  = M >> 5;
    const int r0l  = wr * 16 + (lane >> 2);
    const float mx0 = smax[r0l];
    const float mx1 = smax[r0l + 8];
    const float* Sr0 = S + (size_t)(row0 + r0l) * M + (lane & 3) * 2;
    const float* Sr1 = S + (size_t)(row0 + r0l + 8) * M + (lane & 3) * 2;

    float acc[16][4];
    #pragma unroll
    for (int i = 0; i < 16; i++)
        #pragma unroll
        for (int j = 0; j < 4; j++) acc[i][j] = 0.f;
    float psum0 = 0.f, psum1 = 0.f;

    auto loadB = [&](int ch, int buf) {
        const int m0 = ch << 5;
        const uint32_t Bb = sb + (uint32_t)buf * 32768u;
        #pragma unroll
        for (int g = tid; g < 1024; g += 512) {     // 256 d-rows x 4 x 16B (hi only)
            int r = g >> 2, seg = g & 3;
            const __half* src = HdThi + (size_t)r * M + m0 + seg * 8;
            uint32_t off = (uint32_t)(r * 128 + seg * 16);
            cp16(Bb + (off ^ ((off >> 3) & 0x70)), src);   // SW128, same formula as load
        }
        CP_COMMIT();
    };
    auto loadS = [&](int ch, float2* sp) {
        const int c0 = ch << 5;
        sp[0] = *(const float2*)(Sr0 + c0);
        sp[1] = *(const float2*)(Sr0 + c0 + 8);
        sp[2] = *(const float2*)(Sr0 + c0 + 16);
        sp[3] = *(const float2*)(Sr0 + c0 + 24);
        sp[4] = *(const float2*)(Sr1 + c0);
        sp[5] = *(const float2*)(Sr1 + c0 + 8);
        sp[6] = *(const float2*)(Sr1 + c0 + 16);
        sp[7] = *(const float2*)(Sr1 + c0 + 24);
    };

    float2 spc[8];
    loadB(0, 0);
    loadS(0, spc);

    for (int c = 0; c < nch; c++) {
        float2 spn[8];
        if (c + 1 < nch) {
            loadB(c + 1, (c + 1) & 1);
            loadS(c + 1, spn);
            CP_WAIT1();
        } else {
            CP_WAIT0();
        }
        __syncthreads();

        const uint32_t Bb = sb + (uint32_t)(c & 1) * 32768u;
        #pragma unroll
        for (int ks = 0; ks < 2; ks++) {
            float e00 = __expf(spc[2*ks    ].x - mx0), e01 = __expf(spc[2*ks    ].y - mx0);
            float e02 = __expf(spc[2*ks + 1].x - mx0), e03 = __expf(spc[2*ks + 1].y - mx0);
            float e10 = __expf(spc[4 + 2*ks    ].x - mx1), e11 = __expf(spc[4 + 2*ks    ].y - mx1);
            float e12 = __expf(spc[4 + 2*ks + 1].x - mx1), e13 = __expf(spc[4 + 2*ks + 1].y - mx1);
            psum0 += e00 + e01 + e02 + e03;
            psum1 += e10 + e11 + e12 + e13;
            uint32_t ah[4];
            ah[0] = pack2h(e00, e01); ah[1] = pack2h(e10, e11);
            ah[2] = pack2h(e02, e03); ah[3] = pack2h(e12, e13);
            #pragma unroll
            for (int nt2 = 0; nt2 < 8; nt2++) {
                int r  = wc * 128 + nt2 * 16 + (lm >> 1) * 8 + lr;
                int cb = ks * 32 + (lm & 1) * 16;
                uint32_t b[4];
                LDSM4(b, Bb + (uint32_t)(r * 128) + (uint32_t)(cb ^ ((r & 7) << 4)));
                MMA16816(acc[nt2 * 2    ], ah, b[0], b[1]);
                MMA16816(acc[nt2 * 2 + 1], ah, b[2], b[3]);
            }
        }
        #pragma unroll
        for (int i = 0; i < 8; i++) spc[i] = spn[i];
        __syncthreads();
    }

    psum0 += __shfl_xor_sync(0xffffffffu, psum0, 1);
    psum0 += __shfl_xor_sync(0xffffffffu, psum0, 2);
    psum1 += __shfl_xor_sync(0xffffffffu, psum1, 1);
    psum1 += __shfl_xor_sync(0xffffffffu, psum1, 2);
    if ((lane & 3) == 0 && wc == 0) {
        atomicAdd(&ssum[r0l],     psum0);
        atomicAdd(&ssum[r0l + 8], psum1);
    }
    __syncthreads();
    const float inv0 = 1.f / ssum[r0l];
    const float inv1 = 1.f / ssum[r0l + 8];

    #pragma unroll
    for (int nt2 = 0; nt2 < 8; nt2++) {
        #pragma unroll
        for (int j = 0; j < 2; j++) {
            int col = wc * 128 + nt2 * 16 + j * 8 + (lane & 3) * 2;
            float* a4 = acc[nt2 * 2 + j];
            *(float2*)&O[(size_t)(row0 + r0l)     * d + col] =
                make_float2(a4[0] * inv0, a4[1] * inv0);
            *(float2*)&O[(size_t)(row0 + r0l + 8) * d + col] =
                make_float2(a4[2] * inv1, a4[3] * inv1);
        }
    }
}

// ---------------- prep kernels ----------------
__global__ void split_kernel(const float* __restrict__ in,
                             __half* __restrict__ hi, __half* __restrict__ lo, size_t n)
{
    for (size_t i = (size_t)blockIdx.x * blockDim.x + threadIdx.x; i < n;
         i += (size_t)gridDim.x * blockDim.x) {
        __half h, l; split2h(in[i], h, l);
        hi[i] = h; lo[i] = l;
    }
}

// All small preps in one kernel: Hd split (+HdT hi), V split, U tsplit, rowmax init.
__global__ void prep_small(const float* __restrict__ Hd, const float* __restrict__ V,
                           const float* __restrict__ U,
                           __half* __restrict__ Hdhi, __half* __restrict__ Hdlo,
                           __half* __restrict__ HdThi,
                           __half* __restrict__ Vhi, __half* __restrict__ Vlo,
                           __half* __restrict__ Uthi, __half* __restrict__ Utlo,
                           float* __restrict__ rm)
{
    const int i0 = blockIdx.x * blockDim.x + threadIdx.x;
    const int stride = gridDim.x * blockDim.x;
    for (int t = i0; t < MM * DD; t += stride) {
        __half h, l; split2h(Hd[t], h, l);
        Hdhi[t] = h; Hdlo[t] = l;
        int m = t >> 8, dd = t & 255;   // DD = 256
        HdThi[(size_t)dd * MM + m] = h;
    }
    for (int t = i0; t < KK * DD; t += stride) {
        __half h, l; split2h(V[t], h, l);
        Vhi[t] = h; Vlo[t] = l;
    }
    for (int t = i0; t < DD * KK; t += stride) {
        int r = t >> 9, c = t & 511;    // U[r<256][c<512]
        __half h, l; split2h(U[t], h, l);
        Uthi[(size_t)c * DD + r] = h;
        Utlo[(size_t)c * DD + r] = l;
    }
    for (int t = i0; t < NN; t += stride) rm[t] = -INFINITY;
}

// ---------------- launch ----------------
extern "C" void kernel_launch(void* const* d_in, const int* in_sizes, int n_in,
                              void* d_out, int out_size)
{
    const float* H_rna  = (const float*)d_in[0];
    const float* H_drug = (const float*)d_in[1];
    const float* U      = (const float*)d_in[2];
    const float* V      = (const float*)d_in[3];
    const float* q      = (const float*)d_in[4];
    const float* g_rna  = (const float*)d_in[5];
    const float* b_rna  = (const float*)d_in[6];
    const float* g_drug = (const float*)d_in[7];
    const float* b_drug = (const float*)d_in[8];

    const int K = in_sizes[4];             // 512
    const int d = in_sizes[2] / K;         // 256
    const int N = in_sizes[0] / d;         // 65536
    const int M = in_sizes[1] / d;         // 2048

    float *pS, *pRM;
    __half *pAhi, *pAlo, *pHrhi, *pHrlo, *pHdhi, *pHdlo, *pVhi, *pVlo;
    __half *pDpThi, *pDpTlo, *pHdThi, *pUthi, *pUtlo;
    cudaGetSymbolAddress((void**)&pS,     g_S);
    cudaGetSymbolAddress((void**)&pRM,    g_rowmax);
    cudaGetSymbolAddress((void**)&pAhi,   g_Ahi);
    cudaGetSymbolAddress((void**)&pAlo,   g_Alo);
    cudaGetSymbolAddress((void**)&pHrhi,  g_Hrhi);
    cudaGetSymbolAddress((void**)&pHrlo,  g_Hrlo);
    cudaGetSymbolAddress((void**)&pHdhi,  g_Hdhi);
    cudaGetSymbolAddress((void**)&pHdlo,  g_Hdlo);
    cudaGetSymbolAddress((void**)&pVhi,   g_Vhi);
    cudaGetSymbolAddress((void**)&pVlo,   g_Vlo);
    cudaGetSymbolAddress((void**)&pDpThi, g_DpThi);
    cudaGetSymbolAddress((void**)&pDpTlo, g_DpTlo);
    cudaGetSymbolAddress((void**)&pHdThi, g_HdThi);
    cudaGetSymbolAddress((void**)&pUthi,  g_Uthi);
    cudaGetSymbolAddress((void**)&pUtlo,  g_Utlo);

    const int SMEMSZ = 98304;                    // gemm_hmma: 3 x 32KB
    cudaFuncSetAttribute(gemm_hmma<2>, cudaFuncAttributeMaxDynamicSharedMemorySize, SMEMSZ);
    const int SMEMLN = 3 * 73728 + 512;          // gemm_ln: 3 x 72KB + lnsum
    cudaFuncSetAttribute(gemm_ln, cudaFuncAttributeMaxDynamicSharedMemorySize, SMEMLN);
    const int SMEMPV = 65536 + 1024;             // softmax_pv: 2 x 32KB + smax/ssum
    cudaFuncSetAttribute(softmax_pv, cudaFuncAttributeMaxDynamicSharedMemorySize, SMEMPV);

    // prep
    split_kernel<<<4096, 256>>>(H_rna, pHrhi, pHrlo, (size_t)N * d);
    prep_small<<<512, 256>>>(H_drug, V, U, pHdhi, pHdlo, pHdThi, pVhi, pVlo, pUthi, pUtlo, pRM);

    // stages 1+2 fused: drug (blocks 0..31) -> DpT splits; rna (blocks 32..1055) -> A splits
    const int nblk1 = M / 64;                    // 32
    gemm_ln<<<nblk1 + N / 64, 512, SMEMLN>>>(
        pHdhi, pHdlo, pVhi, pVlo, g_drug, b_drug, pDpThi, pDpTlo, nblk1,
        pHrhi, pHrlo, pUthi, pUtlo, g_rna, b_rna, q, pAhi, pAlo);

    // stage 4: S = A @ Dp -> fp32 [N, M], fused per-row max
    gemm_hmma<2><<<dim3(M / 128, N / 128), 256, SMEMSZ>>>(pAhi, pAlo, pDpThi, pDpTlo, pS, K, M, pRM);

    // stages 5+6: out = softmax(S) @ H_drug
    softmax_pv<<<N / 128, 512, SMEMPV>>>(pS, pHdThi, pRM, (float*)d_out, M, d);
}